// round 2
// baseline (speedup 1.0000x reference)
#include <cuda_runtime.h>
#include <math.h>

#define BATCH 4

// ---------------- scratch (static device arrays; no allocation) ----------------
__device__ float g_xd0[BATCH*1104*10*32];
__device__ float g_cat1[BATCH*1488*20*64];
__device__ float g_xd1[BATCH*552*20*64];
__device__ float g_ll1[BATCH*20*64];
__device__ float g_h1[BATCH*3*20*64];
__device__ float g_ll40[BATCH*40*128];
__device__ float g_mask1[BATCH*20*64];
__device__ float g_upm1[BATCH*20*64];
__device__ float g_cam1[BATCH*40*128];
__device__ float g_wm1[BATCH*40*128];
__device__ float g_feat1[BATCH*744*40*128];
__device__ float g_xa[BATCH*276*40*128];
__device__ float g_h2[BATCH*3*40*128];
__device__ float g_ll80[BATCH*80*256];
__device__ float g_mask2[BATCH*40*128];
__device__ float g_upm2[BATCH*40*128];
__device__ float g_cam2[BATCH*80*256];
__device__ float g_wm2[BATCH*80*256];
__device__ float g_feat0[BATCH*372*80*256];
__device__ float g_xb[BATCH*138*80*256];
__device__ float g_h3[BATCH*3*80*256];
__device__ float g_thr[1];

// ---------------- big conv: 64 OC x (8 rows x 16 cols) tile, 128 threads -------
// thread computes 8 oc x 8 px.  PAD: 0=zero, 1=reflect, 2=edge(replicate)
template<int PAD>
__global__ __launch_bounds__(128)
void conv3x3_big(const float* __restrict__ in, const float* __restrict__ wgt,
                 const float* __restrict__ bias, float* __restrict__ out,
                 int IC, int OC, int H, int W,
                 int leaky, const float* __restrict__ mask)
{
    __shared__ float sW[64*72];    // [oc_local][ic_local*9+t]
    __shared__ float sX[8*190];    // [ic_local][10 rows x 19(pad) cols]

    const int tid  = threadIdx.x;
    const int ocg  = tid >> 4;          // 0..7  (8 oc each)
    const int pxg  = tid & 15;          // 0..15 (8 px each)
    const int trow = pxg >> 1;          // 0..7
    const int tcol = (pxg & 1) << 3;    // 0 or 8

    const int tilesX = W >> 4;
    const int tx = blockIdx.x % tilesX;
    const int ty = blockIdx.x / tilesX;
    const int row0 = ty << 3;
    const int col0 = tx << 4;
    const int oc0  = blockIdx.y << 6;
    const int b    = blockIdx.z;

    const float* inb = in + (size_t)b*IC*H*W;
    const size_t K9 = (size_t)IC*9;

    float acc[8][8];
    #pragma unroll
    for (int j=0;j<8;j++)
        #pragma unroll
        for (int i=0;i<8;i++) acc[j][i]=0.f;

    for (int ic0=0; ic0<IC; ic0+=8) {
        // ---- load input tile: 8 ic x 10 x 18 (with padding resolved here) ----
        for (int i = tid; i < 1440; i += 128) {
            int ici = i / 180;
            int rem = i - ici*180;
            int r = rem / 18;
            int c = rem - r*18;
            int gy = row0 - 1 + r;
            int gx = col0 - 1 + c;
            float v = 0.f;
            int ic = ic0 + ici;
            if (ic < IC) {
                int yy = gy, xx = gx;
                bool ok = true;
                if (PAD == 0) {
                    ok = (gy>=0) && (gy<H) && (gx>=0) && (gx<W);
                } else if (PAD == 1) {
                    yy = gy < 0 ? -gy : (gy >= H ? 2*H-2-gy : gy);
                    xx = gx < 0 ? -gx : (gx >= W ? 2*W-2-gx : gx);
                } else {
                    yy = min(max(gy,0),H-1);
                    xx = min(max(gx,0),W-1);
                }
                if (ok) v = __ldg(inb + (size_t)ic*H*W + yy*W + xx);
            }
            sX[ici*190 + r*19 + c] = v;
        }
        // ---- load weights: 64 oc x (8 ic x 9) ----
        {
            const float* wbase = wgt + (size_t)oc0*K9 + (size_t)ic0*9;
            const int kmax = (int)(K9 - (size_t)ic0*9);
            for (int i = tid; i < 4608; i += 128) {
                int ocl = i / 72;
                int k   = i - ocl*72;
                float v = 0.f;
                if ((oc0+ocl) < OC && k < kmax)
                    v = __ldg(wbase + (size_t)ocl*K9 + k);
                sW[ocl*72 + k] = v;
            }
        }
        __syncthreads();

        #pragma unroll 2
        for (int ici=0; ici<8; ici++) {
            #pragma unroll
            for (int t=0;t<9;t++) {
                const int dy = t/3, dx = t%3;
                float xv[8];
                const float* xp = &sX[ici*190 + (trow+dy)*19 + tcol + dx];
                #pragma unroll
                for (int i=0;i<8;i++) xv[i] = xp[i];
                const float* wp = &sW[(ocg<<3)*72 + ici*9 + t];
                #pragma unroll
                for (int j=0;j<8;j++) {
                    float wv = wp[j*72];
                    #pragma unroll
                    for (int i=0;i<8;i++) acc[j][i] = fmaf(wv, xv[i], acc[j][i]);
                }
            }
        }
        __syncthreads();
    }

    // ---- epilogue: +bias, leaky, optional per-pixel mask ----
    const int orow = row0 + trow;
    if (orow >= H) return;
    #pragma unroll
    for (int j=0;j<8;j++) {
        int oc = oc0 + (ocg<<3) + j;
        if (oc >= OC) break;
        float bv = __ldg(bias + oc);
        float* op = out + ((size_t)b*OC + oc)*H*W + (size_t)orow*W + col0 + tcol;
        #pragma unroll
        for (int i=0;i<8;i++) {
            float v = acc[j][i] + bv;
            if (leaky) v = v > 0.f ? v : 0.2f*v;
            if (mask)  v *= mask[(size_t)b*H*W + (size_t)orow*W + col0 + tcol + i];
            op[i] = v;
        }
    }
}

// ---------------- small conv (OC<=3): thread per pixel ----------------
// maskcoarse: mask sampled at (y/2, x/2) on an H/2 x W/2 grid
template<int NOUT, int PAD>
__global__ void conv3x3_small(const float* __restrict__ in, const float* __restrict__ wgt,
                              const float* __restrict__ bias, float* __restrict__ out,
                              int IC, int H, int W, float scale,
                              const float* __restrict__ mask, int maskcoarse)
{
    int b = blockIdx.z;
    int p = blockIdx.x*blockDim.x + threadIdx.x;
    if (p >= H*W) return;
    int y = p / W, x = p - y*W;
    float acc[NOUT];
    #pragma unroll
    for (int j=0;j<NOUT;j++) acc[j]=0.f;
    const float* inb = in + (size_t)b*IC*H*W;
    for (int ic=0; ic<IC; ic++) {
        const float* ip = inb + (size_t)ic*H*W;
        const float* wp = wgt + (size_t)ic*9;
        #pragma unroll
        for (int t=0;t<9;t++) {
            int yy = y + t/3 - 1, xx = x + t%3 - 1;
            float v;
            if (PAD == 0) {
                v = (yy>=0 && yy<H && xx>=0 && xx<W) ? __ldg(ip + yy*W + xx) : 0.f;
            } else { // edge
                yy = min(max(yy,0),H-1); xx = min(max(xx,0),W-1);
                v = __ldg(ip + yy*W + xx);
            }
            #pragma unroll
            for (int j=0;j<NOUT;j++)
                acc[j] = fmaf(v, __ldg(wp + (size_t)j*IC*9 + t), acc[j]);
        }
    }
    float mval = 1.f;
    if (mask) {
        if (maskcoarse) mval = mask[(size_t)b*(H/2)*(W/2) + (size_t)(y>>1)*(W/2) + (x>>1)];
        else            mval = mask[(size_t)b*H*W + p];
    }
    #pragma unroll
    for (int j=0;j<NOUT;j++)
        out[((size_t)b*NOUT + j)*H*W + p] = (acc[j] + __ldg(bias + j)) * scale * mval;
}

// ---------------- inverse Haar DWT ----------------
__global__ void idwt_k(const float* __restrict__ ll, const float* __restrict__ h,
                       float* __restrict__ out, int Hc, int Wc)
{
    int b = blockIdx.z;
    int p = blockIdx.x*256 + threadIdx.x;
    if (p >= Hc*Wc) return;
    int y = p / Wc, x = p - y*Wc;
    float l  = ll[(size_t)b*Hc*Wc + p];
    const float* hb = h + (size_t)b*3*Hc*Wc;
    float lh = hb[p], hl = hb[Hc*Wc + p], hh = hb[2*Hc*Wc + p];
    float a  = (l + lh)*0.5f, c2 = (l - lh)*0.5f;
    float d2 = (hl + hh)*0.5f, e = (hl - hh)*0.5f;
    float* ob = out + (size_t)b*(2*Hc)*(2*Wc);
    int W2 = 2*Wc;
    ob[(size_t)(2*y)*W2   + 2*x]   = a + d2;
    ob[(size_t)(2*y)*W2   + 2*x+1] = c2 + e;
    ob[(size_t)(2*y+1)*W2 + 2*x]   = a - d2;
    ob[(size_t)(2*y+1)*W2 + 2*x+1] = c2 - e;
}

// ---------------- global (max-min)*0.1 -> thr[0], single block ----------------
__global__ void minmax_k(const float* __restrict__ d, int n, float* __restrict__ thr)
{
    __shared__ float smn[1024], smx[1024];
    int tid = threadIdx.x;
    float mn = 3.4e38f, mx = -3.4e38f;
    for (int i = tid; i < n; i += 1024) { float v = d[i]; mn = fminf(mn,v); mx = fmaxf(mx,v); }
    smn[tid]=mn; smx[tid]=mx; __syncthreads();
    for (int s=512; s>0; s>>=1) {
        if (tid < s) { smn[tid]=fminf(smn[tid],smn[tid+s]); smx[tid]=fmaxf(smx[tid],smx[tid+s]); }
        __syncthreads();
    }
    if (tid==0) thr[0] = (smx[0]-smn[0])*0.1f;
}

// ---------------- mask = (max_c |h_c| > thr) ----------------
__global__ void mask_k(const float* __restrict__ h, const float* __restrict__ thr,
                       float* __restrict__ mask, int Hc, int Wc)
{
    int b = blockIdx.z;
    int p = blockIdx.x*256 + threadIdx.x;
    if (p >= Hc*Wc) return;
    const float* hb = h + (size_t)b*3*Hc*Wc;
    float m = fmaxf(fabsf(hb[p]), fmaxf(fabsf(hb[Hc*Wc+p]), fabsf(hb[2*Hc*Wc+p])));
    mask[(size_t)b*Hc*Wc + p] = (m > thr[0]) ? 1.f : 0.f;
}

// ---------------- 5x5 SAME maxpool>0 on coarse mask ----------------
__global__ void pool_coarse_k(const float* __restrict__ mask, float* __restrict__ upm,
                              int Hc, int Wc)
{
    int b = blockIdx.z;
    int p = blockIdx.x*256 + threadIdx.x;
    if (p >= Hc*Wc) return;
    int y = p / Wc, x = p - y*Wc;
    const float* mb = mask + (size_t)b*Hc*Wc;
    float r = 0.f;
    for (int dy=-2;dy<=2;dy++){ int yy=y+dy; if (yy<0||yy>=Hc) continue;
      for (int dx=-2;dx<=2;dx++){ int xx=x+dx; if (xx<0||xx>=Wc) continue;
        r = fmaxf(r, mb[yy*Wc+xx]); } }
    upm[(size_t)b*Hc*Wc + p] = (r > 0.f) ? 1.f : 0.f;
}

// ---------------- maxpool5>0 and maxpool3>0 over up2x(mask), at fine res ------
__global__ void pool_fine_k(const float* __restrict__ mask, float* __restrict__ cam,
                            float* __restrict__ wm, int Hc, int Wc)
{
    int b = blockIdx.z;
    int Hf = 2*Hc, Wf = 2*Wc;
    int p = blockIdx.x*256 + threadIdx.x;
    if (p >= Hf*Wf) return;
    int y = p / Wf, x = p - y*Wf;
    const float* mb = mask + (size_t)b*Hc*Wc;
    float c5 = 0.f, c3 = 0.f;
    for (int dy=-2;dy<=2;dy++){ int fy=y+dy; if (fy<0||fy>=Hf) continue;
      for (int dx=-2;dx<=2;dx++){ int fx=x+dx; if (fx<0||fx>=Wf) continue;
        float v = mb[(fy>>1)*Wc + (fx>>1)];
        c5 = fmaxf(c5, v);
        if (dy>=-1 && dy<=1 && dx>=-1 && dx<=1) c3 = fmaxf(c3, v);
      } }
    cam[(size_t)b*Hf*Wf + p] = (c5 > 0.f) ? 1.f : 0.f;
    wm [(size_t)b*Hf*Wf + p] = (c3 > 0.f) ? 1.f : 0.f;
}

// ---------------- feat build: cat(up2x(xc * upm), skip) * cam ----------------
__global__ void feat_k(const float* __restrict__ xc, const float* __restrict__ skip,
                       const float* __restrict__ upm, const float* __restrict__ cam,
                       float* __restrict__ out, int C1, int C2, int Hf, int Wf, int total)
{
    int idx = blockIdx.x*256 + threadIdx.x;
    if (idx >= total) return;
    int Wc = Wf >> 1, Hc = Hf >> 1;
    int x = idx % Wf; int t = idx / Wf;
    int y = t % Hf;  t /= Hf;
    int c = t % (C1+C2); int b = t / (C1+C2);
    float v;
    if (c < C1) {
        size_t ci = ((size_t)b*C1 + c)*Hc*Wc + (size_t)(y>>1)*Wc + (x>>1);
        v = xc[ci];
        if (upm) v *= upm[(size_t)b*Hc*Wc + (size_t)(y>>1)*Wc + (x>>1)];
    } else {
        v = skip[((size_t)b*C2 + (c-C1))*Hf*Wf + (size_t)y*Wf + x];
    }
    if (cam) v *= cam[(size_t)b*Hf*Wf + (size_t)y*Wf + x];
    out[idx] = v;
}

// =======================================================================
extern "C" void kernel_launch(void* const* d_in, const int* in_sizes, int n_in,
                              void* d_out, int out_size)
{
    const float* x32      = (const float*)d_in[0];
    const float* x16      = (const float*)d_in[1];
    const float* x8       = (const float*)d_in[2];
    const float* x4       = (const float*)d_in[3];
    const float* conv2_w  = (const float*)d_in[4];
    const float* conv2_b  = (const float*)d_in[5];
    const float* up1_w    = (const float*)d_in[6];
    const float* up1_b    = (const float*)d_in[7];
    const float* w1ll_w   = (const float*)d_in[8];
    const float* w1ll_b   = (const float*)d_in[9];
    const float* w1_w     = (const float*)d_in[10];
    const float* w1_b     = (const float*)d_in[11];
    const float* up2_w    = (const float*)d_in[12];
    const float* up2_b    = (const float*)d_in[13];
    const float* w2_w     = (const float*)d_in[14];
    const float* w2_b     = (const float*)d_in[15];
    const float* up3_w    = (const float*)d_in[16];
    const float* up3_b    = (const float*)d_in[17];
    const float* w3_w     = (const float*)d_in[18];
    const float* w3_b     = (const float*)d_in[19];

    float *xd0,*cat1,*xd1,*ll1,*h1,*ll40,*mask1,*upm1,*cam1,*wm1;
    float *feat1,*xa,*h2,*ll80,*mask2,*upm2,*cam2,*wm2,*feat0,*xb,*h3,*thr;
    cudaGetSymbolAddress((void**)&xd0,  g_xd0);
    cudaGetSymbolAddress((void**)&cat1, g_cat1);
    cudaGetSymbolAddress((void**)&xd1,  g_xd1);
    cudaGetSymbolAddress((void**)&ll1,  g_ll1);
    cudaGetSymbolAddress((void**)&h1,   g_h1);
    cudaGetSymbolAddress((void**)&ll40, g_ll40);
    cudaGetSymbolAddress((void**)&mask1,g_mask1);
    cudaGetSymbolAddress((void**)&upm1, g_upm1);
    cudaGetSymbolAddress((void**)&cam1, g_cam1);
    cudaGetSymbolAddress((void**)&wm1,  g_wm1);
    cudaGetSymbolAddress((void**)&feat1,g_feat1);
    cudaGetSymbolAddress((void**)&xa,   g_xa);
    cudaGetSymbolAddress((void**)&h2,   g_h2);
    cudaGetSymbolAddress((void**)&ll80, g_ll80);
    cudaGetSymbolAddress((void**)&mask2,g_mask2);
    cudaGetSymbolAddress((void**)&upm2, g_upm2);
    cudaGetSymbolAddress((void**)&cam2, g_cam2);
    cudaGetSymbolAddress((void**)&wm2,  g_wm2);
    cudaGetSymbolAddress((void**)&feat0,g_feat0);
    cudaGetSymbolAddress((void**)&xb,   g_xb);
    cudaGetSymbolAddress((void**)&h3,   g_h3);
    cudaGetSymbolAddress((void**)&thr,  g_thr);

    // 1) conv2: 2208 -> 1104, 10x32, edge pad
    conv3x3_big<2><<<dim3(2*2, 18, BATCH), 128>>>(x32, conv2_w, conv2_b, xd0,
                                                  2208, 1104, 10, 32, 0, nullptr);
    // 2) cat1 = concat(up2x(xd0), x16)  -> [4,1488,20,64]
    {
        int total = BATCH*1488*20*64;
        feat_k<<<(total+255)/256, 256>>>(xd0, x16, nullptr, nullptr, cat1,
                                         1104, 384, 20, 64, total);
    }
    // 3) up1: 1488 -> 552, 20x64, reflect, leaky
    conv3x3_big<1><<<dim3(4*3, 9, BATCH), 128>>>(cat1, up1_w, up1_b, xd1,
                                                 1488, 552, 20, 64, 1, nullptr);
    // 4) wave1ll: 8*conv (edge), 5) wave1: 4*conv (zero)
    conv3x3_small<1,2><<<dim3(5,1,BATCH), 256>>>(xd1, w1ll_w, w1ll_b, ll1,
                                                 552, 20, 64, 8.f, nullptr, 0);
    conv3x3_small<3,0><<<dim3(5,1,BATCH), 256>>>(xd1, w1_w, w1_b, h1,
                                                 552, 20, 64, 4.f, nullptr, 0);
    // 6) idwt -> ll40 [4,1,40,128]
    idwt_k<<<dim3(5,1,BATCH), 256>>>(ll1, h1, ll40, 20, 64);
    // 7) thresh from ll40
    minmax_k<<<1, 1024>>>(ll40, BATCH*40*128, thr);
    // 8) mask1 (20x64) from h1
    mask_k<<<dim3(5,1,BATCH), 256>>>(h1, thr, mask1, 20, 64);
    // 9) pooled masks
    pool_coarse_k<<<dim3(5,1,BATCH), 256>>>(mask1, upm1, 20, 64);
    pool_fine_k  <<<dim3(20,1,BATCH), 256>>>(mask1, cam1, wm1, 20, 64);
    // 10) feat1 = cat(up2x(xd1*upm1), x8) * cam1 -> [4,744,40,128]
    {
        int total = BATCH*744*40*128;
        feat_k<<<(total+255)/256, 256>>>(xd1, x8, upm1, cam1, feat1,
                                         552, 192, 40, 128, total);
    }
    // 11) up2: 744 -> 276, 40x128, reflect, leaky, * wm1
    conv3x3_big<1><<<dim3(8*5, 5, BATCH), 128>>>(feat1, up2_w, up2_b, xa,
                                                 744, 276, 40, 128, 1, wm1);
    // 12) h2 = 2*conv(xa) * up2x(mask1)
    conv3x3_small<3,0><<<dim3(20,1,BATCH), 256>>>(xa, w2_w, w2_b, h2,
                                                  276, 40, 128, 2.f, mask1, 1);
    // 13) idwt -> ll80
    idwt_k<<<dim3(20,1,BATCH), 256>>>(ll40, h2, ll80, 40, 128);
    // 14) thresh from ll80
    minmax_k<<<1, 1024>>>(ll80, BATCH*80*256, thr);
    // 15) mask2 (40x128) from h2
    mask_k<<<dim3(20,1,BATCH), 256>>>(h2, thr, mask2, 40, 128);
    // 16) pooled masks level 0
    pool_coarse_k<<<dim3(20,1,BATCH), 256>>>(mask2, upm2, 40, 128);
    pool_fine_k  <<<dim3(80,1,BATCH), 256>>>(mask2, cam2, wm2, 40, 128);
    // 17) feat0 = cat(up2x(xa*upm2), x4) * cam2 -> [4,372,80,256]
    {
        int total = BATCH*372*80*256;
        feat_k<<<(total+255)/256, 256>>>(xa, x4, upm2, cam2, feat0,
                                         276, 96, 80, 256, total);
    }
    // 18) up3: 372 -> 138, 80x256, reflect, leaky, * wm2
    conv3x3_big<1><<<dim3(16*10, 3, BATCH), 128>>>(feat0, up3_w, up3_b, xb,
                                                   372, 138, 80, 256, 1, wm2);
    // 19) h3 = conv(xb) * up2x(mask2)
    conv3x3_small<3,0><<<dim3(80,1,BATCH), 256>>>(xb, w3_w, w3_b, h3,
                                                  138, 80, 256, 1.f, mask2, 1);
    // 20) final idwt -> d_out [4,1,160,512]
    idwt_k<<<dim3(80,1,BATCH), 256>>>(ll80, h3, (float*)d_out, 80, 256);
}

// round 5
// speedup vs baseline: 1.3994x; 1.3994x over previous
#include <cuda_runtime.h>
#include <cuda_bf16.h>
#include <math.h>
#include <stdint.h>

#define BATCH 4

__device__ __forceinline__ uint32_t smem_u32(const void* p){
    uint32_t a; asm("{ .reg .u64 t; cvta.to.shared.u64 t, %1; cvt.u32.u64 %0, t; }":"=r"(a):"l"(p)); return a;
}
__device__ __forceinline__ void ldsm4(uint32_t& r0, uint32_t& r1, uint32_t& r2, uint32_t& r3, uint32_t a){
    asm volatile("ldmatrix.sync.aligned.m8n8.x4.shared.b16 {%0,%1,%2,%3}, [%4];"
        :"=r"(r0),"=r"(r1),"=r"(r2),"=r"(r3):"r"(a));
}
__device__ __forceinline__ void mma16816(float* c, const uint32_t* a, const uint32_t* b){
    asm volatile("mma.sync.aligned.m16n8k16.row.col.f32.bf16.bf16.f32 "
        "{%0,%1,%2,%3}, {%4,%5,%6,%7}, {%8,%9}, {%0,%1,%2,%3};"
        : "+f"(c[0]),"+f"(c[1]),"+f"(c[2]),"+f"(c[3])
        : "r"(a[0]),"r"(a[1]),"r"(a[2]),"r"(a[3]),"r"(b[0]),"r"(b[1]));
}

// ---------------- scratch ----------------
__device__ float g_xd0[BATCH*1104*10*32];
__device__ float g_cat1[BATCH*1488*20*64];
__device__ float g_xd1[BATCH*552*20*64];
__device__ float g_ll1[BATCH*20*64];
__device__ float g_h1[BATCH*3*20*64];
__device__ float g_ll40[BATCH*40*128];
__device__ float g_mask1[BATCH*20*64];
__device__ float g_upm1[BATCH*20*64];
__device__ float g_cam1[BATCH*40*128];
__device__ float g_wm1[BATCH*40*128];
__device__ float g_feat1[BATCH*744*40*128];
__device__ float g_xa[BATCH*276*40*128];
__device__ float g_h2[BATCH*3*40*128];
__device__ float g_ll80[BATCH*80*256];
__device__ float g_mask2[BATCH*40*128];
__device__ float g_upm2[BATCH*40*128];
__device__ float g_cam2[BATCH*80*256];
__device__ float g_wm2[BATCH*80*256];
__device__ float g_feat0[BATCH*372*80*256];
__device__ float g_xb[BATCH*138*80*256];
__device__ float g_h3[BATCH*3*80*256];
__device__ float g_thr[1];
__device__ __align__(16) __nv_bfloat16 g_w2h[1152*19872];
__device__ __align__(16) __nv_bfloat16 g_w2l[1152*19872];
__device__ __align__(16) __nv_bfloat16 g_u1h[640*13408];
__device__ __align__(16) __nv_bfloat16 g_u1l[640*13408];
__device__ __align__(16) __nv_bfloat16 g_u2h[384*6720];
__device__ __align__(16) __nv_bfloat16 g_u2l[384*6720];
__device__ __align__(16) __nv_bfloat16 g_u3h[256*3360];
__device__ __align__(16) __nv_bfloat16 g_u3l[256*3360];

// ---------------- weight pack ----------------
__global__ void pack_w_k(const float* __restrict__ w, __nv_bfloat16* __restrict__ hi,
                         __nv_bfloat16* __restrict__ lo, int OC, int K, int Kpad, int total)
{
    int i = blockIdx.x*256 + threadIdx.x;
    if (i >= total) return;
    int r = i / Kpad, k = i - r*Kpad;
    float v = (r < OC && k < K) ? w[(size_t)r*K + k] : 0.f;
    __nv_bfloat16 h = __float2bfloat16(v);
    hi[i] = h;
    lo[i] = __float2bfloat16(v - __bfloat162float(h));
}

// ---------------- HMMA implicit-GEMM conv ----------------
// smem: 4 planes (Ah, Al, Bh, Bl), each 128 rows x 80B (32 bf16 + pad)
#define ROWB 80
#define S_AH 0
#define S_AL 10240
#define S_BH 20480
#define S_BL 30720

template<int PAD>  // 1 reflect, 2 edge
__global__ __launch_bounds__(256, 2)
void conv_hmma(const __nv_bfloat16* __restrict__ Ah, const __nv_bfloat16* __restrict__ Al,
               const float* __restrict__ in, float* __restrict__ out,
               int IC, int OC, int H, int W, int Kpad, int S)
{
    __shared__ __align__(16) unsigned char sm[40960];
    const uint32_t sb = smem_u32(sm);
    const int tid = threadIdx.x, wid = tid >> 5, lane = tid & 31;
    const int HW = H * W;
    const int n0 = blockIdx.x * 128;
    const int Mtiles = gridDim.y / S;
    const int mt_id = blockIdx.y % Mtiles, ks = blockIdx.y / Mtiles;
    const int m0 = mt_id * 128;
    const int b = blockIdx.z;

    const int chunks = Kpad >> 5;
    const int cseg = (chunks + S - 1) / S;
    const int c0 = ks * cseg, c1 = min(chunks, c0 + cseg);

    const float* inb = in + (size_t)b * IC * HW;
    const int wm = (wid >> 2) * 64, wn = (wid & 3) * 32;

    float acc[4][4][4];
    #pragma unroll
    for (int i=0;i<4;i++) for (int j=0;j<4;j++) for (int k=0;k<4;k++) acc[i][j][k]=0.f;

    const int mloc = tid >> 1, kh = tid & 1;  // load roles
    const int nglob = n0 + mloc;
    int py = nglob < HW ? nglob / W : 0;
    int px_ = nglob < HW ? nglob - py*W : 0;

    for (int c = c0; c < c1; ++c) {
        const int kc = c << 5;
        // ---- A: weights hi/lo, 128 x 32 ----
        {
            const uint4* pH = (const uint4*)(Ah + (size_t)(m0+mloc)*Kpad + kc + kh*16);
            const uint4* pL = (const uint4*)(Al + (size_t)(m0+mloc)*Kpad + kc + kh*16);
            uint4 h0 = pH[0], h1 = pH[1], l0 = pL[0], l1 = pL[1];
            int d = mloc*ROWB + kh*32;
            *(uint4*)(sm + d + S_AH) = h0; *(uint4*)(sm + d + S_AH + 16) = h1;
            *(uint4*)(sm + d + S_AL) = l0; *(uint4*)(sm + d + S_AL + 16) = l1;
        }
        // ---- B: im2col gather + split ----
        {
            uint32_t h4[8], l4[8];
            if (nglob < HW) {
                int k = kc + kh*16;
                int ic = k / 9, t = k - ic*9;
                #pragma unroll
                for (int e = 0; e < 16; ++e) {
                    float v = 0.f;
                    if (ic < IC) {
                        int t3 = t/3, dy = t3-1, dx = t - t3*3 - 1;
                        int yy = py+dy, xx = px_+dx;
                        if (PAD == 1) {
                            yy = yy<0 ? -yy : (yy>=H ? 2*H-2-yy : yy);
                            xx = xx<0 ? -xx : (xx>=W ? 2*W-2-xx : xx);
                        } else {
                            yy = min(max(yy,0),H-1); xx = min(max(xx,0),W-1);
                        }
                        v = __ldg(inb + (size_t)ic*HW + yy*W + xx);
                    }
                    __nv_bfloat16 hb = __float2bfloat16(v);
                    __nv_bfloat16 lb = __float2bfloat16(v - __bfloat162float(hb));
                    uint32_t hu = *(unsigned short*)&hb, lu = *(unsigned short*)&lb;
                    if (e & 1) { h4[e>>1] |= hu << 16; l4[e>>1] |= lu << 16; }
                    else       { h4[e>>1] = hu;        l4[e>>1] = lu; }
                    if (++t == 9) { t = 0; ++ic; }
                }
            } else {
                #pragma unroll
                for (int e = 0; e < 8; ++e) { h4[e] = 0; l4[e] = 0; }
            }
            int d = mloc*ROWB + kh*32;
            *(uint4*)(sm + d + S_BH) = make_uint4(h4[0],h4[1],h4[2],h4[3]);
            *(uint4*)(sm + d + S_BH + 16) = make_uint4(h4[4],h4[5],h4[6],h4[7]);
            *(uint4*)(sm + d + S_BL) = make_uint4(l4[0],l4[1],l4[2],l4[3]);
            *(uint4*)(sm + d + S_BL + 16) = make_uint4(l4[4],l4[5],l4[6],l4[7]);
        }
        __syncthreads();
        // ---- compute: 2 k16 steps ----
        #pragma unroll
        for (int kk = 0; kk < 2; ++kk) {
            uint32_t bh[4][2], bl[4][2];
            #pragma unroll
            for (int nt2 = 0; nt2 < 2; ++nt2) {
                int g = lane >> 3;
                int brow = wn + nt2*16 + (lane & 7) + ((g & 2) ? 8 : 0);
                uint32_t baddr = sb + brow*ROWB + kk*32 + ((g & 1) ? 16 : 0);
                // non-trans: smem row (pixel n, K contiguous) == column of col-major B
                ldsm4(bh[nt2*2][0], bh[nt2*2][1], bh[nt2*2+1][0], bh[nt2*2+1][1], baddr + S_BH);
                ldsm4(bl[nt2*2][0], bl[nt2*2][1], bl[nt2*2+1][0], bl[nt2*2+1][1], baddr + S_BL);
            }
            #pragma unroll
            for (int mt = 0; mt < 4; ++mt) {
                int arow = wm + mt*16 + (lane & 15);
                uint32_t aaddr = sb + arow*ROWB + kk*32 + ((lane >> 4) ? 16 : 0);
                uint32_t ah[4], al[4];
                ldsm4(ah[0], ah[1], ah[2], ah[3], aaddr + S_AH);
                ldsm4(al[0], al[1], al[2], al[3], aaddr + S_AL);
                #pragma unroll
                for (int nt = 0; nt < 4; ++nt) {
                    mma16816(acc[mt][nt], ah, bh[nt]);
                    mma16816(acc[mt][nt], ah, bl[nt]);
                    mma16816(acc[mt][nt], al, bh[nt]);
                }
            }
        }
        __syncthreads();
    }

    // ---- epilogue ----
    float* ob = out + (size_t)b * OC * HW;
    const bool direct = (S == 1);
    #pragma unroll
    for (int mt = 0; mt < 4; ++mt) {
        #pragma unroll
        for (int nt = 0; nt < 4; ++nt) {
            #pragma unroll
            for (int cr = 0; cr < 4; ++cr) {
                int r = wm + mt*16 + (lane >> 2) + ((cr >= 2) ? 8 : 0);
                int col = wn + nt*8 + (lane & 3)*2 + (cr & 1);
                int oc = m0 + r, px = n0 + col;
                if (oc < OC && px < HW) {
                    float v = acc[mt][nt][cr];
                    if (direct) ob[(size_t)oc*HW + px] = v;
                    else atomicAdd(ob + (size_t)oc*HW + px, v);
                }
            }
        }
    }
}

// ---------------- finalize big: buf = leaky(buf+bias) * mask ----------------
__global__ void finalize_big(float* __restrict__ buf, const float* __restrict__ bias,
                             const float* __restrict__ mask, int C, int HW, int leaky, int total)
{
    int i = blockIdx.x*256 + threadIdx.x;
    if (i >= total) return;
    int p = i % HW, t = i / HW, c = t % C, b = t / C;
    float v = buf[i] + bias[c];
    if (leaky) v = v > 0.f ? v : 0.2f*v;
    if (mask) v *= mask[(size_t)b*HW + p];
    buf[i] = v;
}

// ---------------- small conv partial (IC-split, atomic) ----------------
template<int NOUT, int PAD>
__global__ void conv_small_part(const float* __restrict__ in, const float* __restrict__ wgt,
                                float* __restrict__ acc, int IC, int nsp, int H, int W)
{
    int b = blockIdx.z, sp = blockIdx.y;
    int HW = H*W;
    int p = blockIdx.x*128 + threadIdx.x;
    if (p >= HW) return;
    int y = p / W, x = p - y*W;
    int icPer = (IC + nsp - 1)/nsp, ic0 = sp*icPer, ic1 = min(IC, ic0+icPer);
    float a[NOUT];
    #pragma unroll
    for (int j = 0; j < NOUT; ++j) a[j] = 0.f;
    const float* inb = in + (size_t)b*IC*HW;
    for (int ic = ic0; ic < ic1; ++ic) {
        const float* ip = inb + (size_t)ic*HW;
        const float* wp = wgt + (size_t)ic*9;
        #pragma unroll
        for (int t = 0; t < 9; ++t) {
            int yy = y + t/3 - 1, xx = x + t%3 - 1;
            float v;
            if (PAD == 0) v = (yy>=0 && yy<H && xx>=0 && xx<W) ? __ldg(ip + yy*W + xx) : 0.f;
            else { yy = min(max(yy,0),H-1); xx = min(max(xx,0),W-1); v = __ldg(ip + yy*W + xx); }
            #pragma unroll
            for (int j = 0; j < NOUT; ++j)
                a[j] = fmaf(v, __ldg(wp + (size_t)j*IC*9 + t), a[j]);
        }
    }
    #pragma unroll
    for (int j = 0; j < NOUT; ++j)
        atomicAdd(acc + ((size_t)b*NOUT + j)*HW + p, a[j]);
}

__global__ void finalize_small(float* __restrict__ buf, const float* __restrict__ bias,
                               const float* __restrict__ mask, int NOUT, int H, int W,
                               float scale, int total)
{
    int i = blockIdx.x*256 + threadIdx.x;
    if (i >= total) return;
    int HW = H*W;
    int p = i % HW, t = i / HW, c = t % NOUT, b = t / NOUT;
    float v = (buf[i] + bias[c]) * scale;
    if (mask) {
        int y = p / W, x = p - y*W;
        v *= mask[(size_t)b*(HW/4) + (y>>1)*(W>>1) + (x>>1)];
    }
    buf[i] = v;
}

// ---------------- glue ----------------
__global__ void idwt_k(const float* __restrict__ ll, const float* __restrict__ h,
                       float* __restrict__ out, int Hc, int Wc)
{
    int b = blockIdx.z;
    int p = blockIdx.x*256 + threadIdx.x;
    if (p >= Hc*Wc) return;
    int y = p / Wc, x = p - y*Wc;
    float l = ll[(size_t)b*Hc*Wc + p];
    const float* hb = h + (size_t)b*3*Hc*Wc;
    float lh = hb[p], hl = hb[Hc*Wc+p], hh = hb[2*Hc*Wc+p];
    float a = (l+lh)*0.5f, c2 = (l-lh)*0.5f, d2 = (hl+hh)*0.5f, e = (hl-hh)*0.5f;
    float* ob = out + (size_t)b*(2*Hc)*(2*Wc);
    int W2 = 2*Wc;
    ob[(size_t)(2*y)*W2 + 2*x]     = a + d2;
    ob[(size_t)(2*y)*W2 + 2*x+1]   = c2 + e;
    ob[(size_t)(2*y+1)*W2 + 2*x]   = a - d2;
    ob[(size_t)(2*y+1)*W2 + 2*x+1] = c2 - e;
}
__global__ void minmax_k(const float* __restrict__ d, int n, float* __restrict__ thr)
{
    __shared__ float smn[1024], smx[1024];
    int tid = threadIdx.x;
    float mn = 3.4e38f, mx = -3.4e38f;
    for (int i = tid; i < n; i += 1024) { float v = d[i]; mn = fminf(mn,v); mx = fmaxf(mx,v); }
    smn[tid]=mn; smx[tid]=mx; __syncthreads();
    for (int s=512; s>0; s>>=1) {
        if (tid<s){ smn[tid]=fminf(smn[tid],smn[tid+s]); smx[tid]=fmaxf(smx[tid],smx[tid+s]); }
        __syncthreads();
    }
    if (tid==0) thr[0] = (smx[0]-smn[0])*0.1f;
}
__global__ void mask_k(const float* __restrict__ h, const float* __restrict__ thr,
                       float* __restrict__ mask, int Hc, int Wc)
{
    int b = blockIdx.z;
    int p = blockIdx.x*256 + threadIdx.x;
    if (p >= Hc*Wc) return;
    const float* hb = h + (size_t)b*3*Hc*Wc;
    float m = fmaxf(fabsf(hb[p]), fmaxf(fabsf(hb[Hc*Wc+p]), fabsf(hb[2*Hc*Wc+p])));
    mask[(size_t)b*Hc*Wc + p] = (m > thr[0]) ? 1.f : 0.f;
}
__global__ void pool_coarse_k(const float* __restrict__ mask, float* __restrict__ upm, int Hc, int Wc)
{
    int b = blockIdx.z;
    int p = blockIdx.x*256 + threadIdx.x;
    if (p >= Hc*Wc) return;
    int y = p / Wc, x = p - y*Wc;
    const float* mb = mask + (size_t)b*Hc*Wc;
    float r = 0.f;
    for (int dy=-2;dy<=2;dy++){ int yy=y+dy; if (yy<0||yy>=Hc) continue;
      for (int dx=-2;dx<=2;dx++){ int xx=x+dx; if (xx<0||xx>=Wc) continue;
        r = fmaxf(r, mb[yy*Wc+xx]); } }
    upm[(size_t)b*Hc*Wc + p] = (r > 0.f) ? 1.f : 0.f;
}
__global__ void pool_fine_k(const float* __restrict__ mask, float* __restrict__ cam,
                            float* __restrict__ wm, int Hc, int Wc)
{
    int b = blockIdx.z;
    int Hf = 2*Hc, Wf = 2*Wc;
    int p = blockIdx.x*256 + threadIdx.x;
    if (p >= Hf*Wf) return;
    int y = p / Wf, x = p - y*Wf;
    const float* mb = mask + (size_t)b*Hc*Wc;
    float c5 = 0.f, c3 = 0.f;
    for (int dy=-2;dy<=2;dy++){ int fy=y+dy; if (fy<0||fy>=Hf) continue;
      for (int dx=-2;dx<=2;dx++){ int fx=x+dx; if (fx<0||fx>=Wf) continue;
        float v = mb[(fy>>1)*Wc + (fx>>1)];
        c5 = fmaxf(c5, v);
        if (dy>=-1 && dy<=1 && dx>=-1 && dx<=1) c3 = fmaxf(c3, v);
      } }
    cam[(size_t)b*Hf*Wf + p] = (c5 > 0.f) ? 1.f : 0.f;
    wm [(size_t)b*Hf*Wf + p] = (c3 > 0.f) ? 1.f : 0.f;
}
__global__ void feat_k(const float* __restrict__ xc, const float* __restrict__ skip,
                       const float* __restrict__ upm, const float* __restrict__ cam,
                       float* __restrict__ out, int C1, int C2, int Hf, int Wf, int total)
{
    int idx = blockIdx.x*256 + threadIdx.x;
    if (idx >= total) return;
    int Wc = Wf >> 1, Hc = Hf >> 1;
    int x = idx % Wf; int t = idx / Wf;
    int y = t % Hf;  t /= Hf;
    int c = t % (C1+C2); int b = t / (C1+C2);
    float v;
    if (c < C1) {
        v = xc[((size_t)b*C1 + c)*Hc*Wc + (size_t)(y>>1)*Wc + (x>>1)];
        if (upm) v *= upm[(size_t)b*Hc*Wc + (size_t)(y>>1)*Wc + (x>>1)];
    } else {
        v = skip[((size_t)b*C2 + (c-C1))*Hf*Wf + (size_t)y*Wf + x];
    }
    if (cam) v *= cam[(size_t)b*Hf*Wf + (size_t)y*Wf + x];
    out[idx] = v;
}

// =======================================================================
extern "C" void kernel_launch(void* const* d_in, const int* in_sizes, int n_in,
                              void* d_out, int out_size)
{
    const float* x32 = (const float*)d_in[0];
    const float* x16 = (const float*)d_in[1];
    const float* x8  = (const float*)d_in[2];
    const float* x4  = (const float*)d_in[3];
    const float* c2w = (const float*)d_in[4];  const float* c2b = (const float*)d_in[5];
    const float* u1w = (const float*)d_in[6];  const float* u1b = (const float*)d_in[7];
    const float* wllw= (const float*)d_in[8];  const float* wllb= (const float*)d_in[9];
    const float* w1w = (const float*)d_in[10]; const float* w1b = (const float*)d_in[11];
    const float* u2w = (const float*)d_in[12]; const float* u2b = (const float*)d_in[13];
    const float* w2w = (const float*)d_in[14]; const float* w2b = (const float*)d_in[15];
    const float* u3w = (const float*)d_in[16]; const float* u3b = (const float*)d_in[17];
    const float* w3w = (const float*)d_in[18]; const float* w3b = (const float*)d_in[19];

    float *xd0,*cat1,*xd1,*ll1,*h1,*ll40,*mask1,*upm1,*cam1,*wm1;
    float *feat1,*xa,*h2,*ll80,*mask2,*upm2,*cam2,*wm2,*feat0,*xb,*h3,*thr;
    __nv_bfloat16 *w2h,*w2l,*p1h,*p1l,*p2h,*p2l,*p3h,*p3l;
    cudaGetSymbolAddress((void**)&xd0,g_xd0);   cudaGetSymbolAddress((void**)&cat1,g_cat1);
    cudaGetSymbolAddress((void**)&xd1,g_xd1);   cudaGetSymbolAddress((void**)&ll1,g_ll1);
    cudaGetSymbolAddress((void**)&h1,g_h1);     cudaGetSymbolAddress((void**)&ll40,g_ll40);
    cudaGetSymbolAddress((void**)&mask1,g_mask1); cudaGetSymbolAddress((void**)&upm1,g_upm1);
    cudaGetSymbolAddress((void**)&cam1,g_cam1); cudaGetSymbolAddress((void**)&wm1,g_wm1);
    cudaGetSymbolAddress((void**)&feat1,g_feat1); cudaGetSymbolAddress((void**)&xa,g_xa);
    cudaGetSymbolAddress((void**)&h2,g_h2);     cudaGetSymbolAddress((void**)&ll80,g_ll80);
    cudaGetSymbolAddress((void**)&mask2,g_mask2); cudaGetSymbolAddress((void**)&upm2,g_upm2);
    cudaGetSymbolAddress((void**)&cam2,g_cam2); cudaGetSymbolAddress((void**)&wm2,g_wm2);
    cudaGetSymbolAddress((void**)&feat0,g_feat0); cudaGetSymbolAddress((void**)&xb,g_xb);
    cudaGetSymbolAddress((void**)&h3,g_h3);     cudaGetSymbolAddress((void**)&thr,g_thr);
    cudaGetSymbolAddress((void**)&w2h,g_w2h);   cudaGetSymbolAddress((void**)&w2l,g_w2l);
    cudaGetSymbolAddress((void**)&p1h,g_u1h);   cudaGetSymbolAddress((void**)&p1l,g_u1l);
    cudaGetSymbolAddress((void**)&p2h,g_u2h);   cudaGetSymbolAddress((void**)&p2l,g_u2l);
    cudaGetSymbolAddress((void**)&p3h,g_u3h);   cudaGetSymbolAddress((void**)&p3l,g_u3l);

    // pack weights: [Mpad, Kpad] hi/lo
    { int t=1152*19872; pack_w_k<<<(t+255)/256,256>>>(c2w, w2h, w2l, 1104, 19872, 19872, t); }
    { int t=640*13408;  pack_w_k<<<(t+255)/256,256>>>(u1w, p1h, p1l, 552, 13392, 13408, t); }
    { int t=384*6720;   pack_w_k<<<(t+255)/256,256>>>(u2w, p2h, p2l, 276, 6696, 6720, t); }
    { int t=256*3360;   pack_w_k<<<(t+255)/256,256>>>(u3w, p3h, p3l, 138, 3348, 3360, t); }

    // zero atomic accumulators
    cudaMemsetAsync(xd0, 0, sizeof(g_xd0), 0);
    cudaMemsetAsync(xd1, 0, sizeof(g_xd1), 0);
    cudaMemsetAsync(ll1, 0, sizeof(g_ll1), 0);
    cudaMemsetAsync(h1,  0, sizeof(g_h1), 0);
    cudaMemsetAsync(h2,  0, sizeof(g_h2), 0);
    cudaMemsetAsync(h3,  0, sizeof(g_h3), 0);

    // conv2 (edge): 2208->1104, 10x32, Mtiles=9, Ntiles=3, S=4
    conv_hmma<2><<<dim3(3, 9*4, BATCH), 256>>>(w2h, w2l, x32, xd0, 2208, 1104, 10, 32, 19872, 4);
    finalize_big<<<(BATCH*1104*320+255)/256,256>>>(xd0, c2b, nullptr, 1104, 320, 0, BATCH*1104*320);
    // cat1
    { int t = BATCH*1488*20*64;
      feat_k<<<(t+255)/256,256>>>(xd0, x16, nullptr, nullptr, cat1, 1104, 384, 20, 64, t); }
    // up1 (reflect): 1488->552, 20x64, Mtiles=5, Ntiles=10, S=2
    conv_hmma<1><<<dim3(10, 5*2, BATCH), 256>>>(p1h, p1l, cat1, xd1, 1488, 552, 20, 64, 13408, 2);
    finalize_big<<<(BATCH*552*1280+255)/256,256>>>(xd1, u1b, nullptr, 552, 1280, 1, BATCH*552*1280);
    // wave1ll (edge, x8) / wave1 (zero, x4)
    conv_small_part<1,2><<<dim3(10,12,BATCH),128>>>(xd1, wllw, ll1, 552, 12, 20, 64);
    conv_small_part<3,0><<<dim3(10,12,BATCH),128>>>(xd1, w1w, h1, 552, 12, 20, 64);
    finalize_small<<<(BATCH*1280+255)/256,256>>>(ll1, wllb, nullptr, 1, 20, 64, 8.f, BATCH*1280);
    finalize_small<<<(BATCH*3*1280+255)/256,256>>>(h1, w1b, nullptr, 3, 20, 64, 4.f, BATCH*3*1280);
    idwt_k<<<dim3(5,1,BATCH),256>>>(ll1, h1, ll40, 20, 64);
    minmax_k<<<1,1024>>>(ll40, BATCH*40*128, thr);
    mask_k<<<dim3(5,1,BATCH),256>>>(h1, thr, mask1, 20, 64);
    pool_coarse_k<<<dim3(5,1,BATCH),256>>>(mask1, upm1, 20, 64);
    pool_fine_k<<<dim3(20,1,BATCH),256>>>(mask1, cam1, wm1, 20, 64);
    // feat1 + up2 (reflect): 744->276, 40x128, Mtiles=3, Ntiles=40, S=1
    { int t = BATCH*744*40*128;
      feat_k<<<(t+255)/256,256>>>(xd1, x8, upm1, cam1, feat1, 552, 192, 40, 128, t); }
    conv_hmma<1><<<dim3(40, 3, BATCH), 256>>>(p2h, p2l, feat1, xa, 744, 276, 40, 128, 6720, 1);
    finalize_big<<<(BATCH*276*5120+255)/256,256>>>(xa, u2b, wm1, 276, 5120, 1, BATCH*276*5120);
    // h2
    conv_small_part<3,0><<<dim3(40,8,BATCH),128>>>(xa, w2w, h2, 276, 8, 40, 128);
    finalize_small<<<(BATCH*3*5120+255)/256,256>>>(h2, w2b, mask1, 3, 40, 128, 2.f, BATCH*3*5120);
    idwt_k<<<dim3(20,1,BATCH),256>>>(ll40, h2, ll80, 40, 128);
    minmax_k<<<1,1024>>>(ll80, BATCH*80*256, thr);
    mask_k<<<dim3(20,1,BATCH),256>>>(h2, thr, mask2, 40, 128);
    pool_coarse_k<<<dim3(20,1,BATCH),256>>>(mask2, upm2, 40, 128);
    pool_fine_k<<<dim3(80,1,BATCH),256>>>(mask2, cam2, wm2, 40, 128);
    // feat0 + up3 (reflect): 372->138, 80x256, Mtiles=2, Ntiles=160, S=1
    { int t = BATCH*372*80*256;
      feat_k<<<(t+255)/256,256>>>(xa, x4, upm2, cam2, feat0, 276, 96, 80, 256, t); }
    conv_hmma<1><<<dim3(160, 2, BATCH), 256>>>(p3h, p3l, feat0, xb, 372, 138, 80, 256, 3360, 1);
    finalize_big<<<(BATCH*138*20480+255)/256,256>>>(xb, u3b, wm2, 138, 20480, 1, BATCH*138*20480);
    // h3
    conv_small_part<3,0><<<dim3(160,4,BATCH),128>>>(xb, w3w, h3, 138, 4, 80, 256);
    finalize_small<<<(BATCH*3*20480+255)/256,256>>>(h3, w3b, mask2, 3, 80, 256, 1.f, BATCH*3*20480);
    idwt_k<<<dim3(80,1,BATCH),256>>>(ll80, h3, (float*)d_out, 80, 256);
}

// round 6
// speedup vs baseline: 2.1287x; 1.5211x over previous
#include <cuda_runtime.h>
#include <cuda_bf16.h>
#include <math.h>
#include <stdint.h>

#define BATCH 4

__device__ __forceinline__ uint32_t smem_u32(const void* p){
    uint32_t a; asm("{ .reg .u64 t; cvta.to.shared.u64 t, %1; cvt.u32.u64 %0, t; }":"=r"(a):"l"(p)); return a;
}
__device__ __forceinline__ void ldsm4(uint32_t& r0, uint32_t& r1, uint32_t& r2, uint32_t& r3, uint32_t a){
    asm volatile("ldmatrix.sync.aligned.m8n8.x4.shared.b16 {%0,%1,%2,%3}, [%4];"
        :"=r"(r0),"=r"(r1),"=r"(r2),"=r"(r3):"r"(a));
}
__device__ __forceinline__ void mma16816(float* c, const uint32_t* a, const uint32_t* b){
    asm volatile("mma.sync.aligned.m16n8k16.row.col.f32.bf16.bf16.f32 "
        "{%0,%1,%2,%3}, {%4,%5,%6,%7}, {%8,%9}, {%0,%1,%2,%3};"
        : "+f"(c[0]),"+f"(c[1]),"+f"(c[2]),"+f"(c[3])
        : "r"(a[0]),"r"(a[1]),"r"(a[2]),"r"(a[3]),"r"(b[0]),"r"(b[1]));
}
__device__ __forceinline__ uint32_t packf(float v){
    __nv_bfloat16 h = __float2bfloat16(v);
    __nv_bfloat16 l = __float2bfloat16(v - __bfloat162float(h));
    return (uint32_t)*(unsigned short*)&h | ((uint32_t)*(unsigned short*)&l << 16);
}

// ---------------- scratch ----------------
__device__ float g_xd0[BATCH*1104*10*32];
__device__ float g_xd1[BATCH*552*20*64];
__device__ float g_ll1[BATCH*20*64];
__device__ float g_h1[BATCH*3*20*64];
__device__ float g_ll40[BATCH*40*128];
__device__ float g_mask1[BATCH*20*64];
__device__ float g_upm1[BATCH*20*64];
__device__ float g_cam1[BATCH*40*128];
__device__ float g_wm1[BATCH*40*128];
__device__ float g_xa[BATCH*276*40*128];
__device__ float g_h2[BATCH*3*40*128];
__device__ float g_ll80[BATCH*80*256];
__device__ float g_mask2[BATCH*40*128];
__device__ float g_upm2[BATCH*40*128];
__device__ float g_cam2[BATCH*80*256];
__device__ float g_wm2[BATCH*80*256];
__device__ float g_xb[BATCH*138*80*256];
__device__ float g_h3[BATCH*3*80*256];
__device__ float g_thr[1];
// packed u32 (bf16 hi | lo<<16) conv inputs
__device__ __align__(16) uint32_t g_px32[BATCH*2208*10*32];
__device__ __align__(16) uint32_t g_cat1[BATCH*1488*20*64];
__device__ __align__(16) uint32_t g_feat1[BATCH*744*40*128];
__device__ __align__(16) uint32_t g_feat0[BATCH*372*80*256];
// packed weights (hi/lo planes), K reordered as t*ICpad+ic
__device__ __align__(16) __nv_bfloat16 g_w2h[1152*20160];
__device__ __align__(16) __nv_bfloat16 g_w2l[1152*20160];
__device__ __align__(16) __nv_bfloat16 g_u1h[640*13824];
__device__ __align__(16) __nv_bfloat16 g_u1l[640*13824];
__device__ __align__(16) __nv_bfloat16 g_u2h[384*6912];
__device__ __align__(16) __nv_bfloat16 g_u2l[384*6912];
__device__ __align__(16) __nv_bfloat16 g_u3h[256*3456];
__device__ __align__(16) __nv_bfloat16 g_u3l[256*3456];

// ---------------- weight pack: w[oc, ic*9+t] -> planes[ocpad, t*ICpad+ic] ----------------
// grid: (OCpad*ICpad/256, 9)
__global__ void pack_w_k(const float* __restrict__ w, __nv_bfloat16* __restrict__ hi,
                         __nv_bfloat16* __restrict__ lo, int OC, int IC, int ICpad, int Kpad, int totRC)
{
    int i = blockIdx.x*256 + threadIdx.x;
    if (i >= totRC) return;
    int t = blockIdx.y;
    int r = i / ICpad, ic = i - r*ICpad;
    float v = (r < OC && ic < IC) ? w[(size_t)r*IC*9 + ic*9 + t] : 0.f;
    __nv_bfloat16 h = __float2bfloat16(v);
    size_t o = (size_t)r*Kpad + t*ICpad + ic;
    hi[o] = h;
    lo[o] = __float2bfloat16(v - __bfloat162float(h));
}

// ---------------- input pack: fp32 -> packed u32 ----------------
__global__ void pack_x_k(const float* __restrict__ x, uint32_t* __restrict__ o, int total)
{
    int i = blockIdx.x*256 + threadIdx.x;
    if (i < total) o[i] = packf(x[i]);
}

// ---------------- feat build + pack: cat(up2x(xc*upm), skip)*cam -> packed u32 ----------------
__global__ void feat_pack_k(const float* __restrict__ xc, const float* __restrict__ skip,
                            const float* __restrict__ upm, const float* __restrict__ cam,
                            uint32_t* __restrict__ out, int C1, int C2, int Hf, int Wf, int total)
{
    int idx = blockIdx.x*256 + threadIdx.x;
    if (idx >= total) return;
    int Wc = Wf >> 1, Hc = Hf >> 1;
    int x = idx % Wf; int t = idx / Wf;
    int y = t % Hf;  t /= Hf;
    int c = t % (C1+C2); int b = t / (C1+C2);
    float v;
    if (c < C1) {
        v = xc[((size_t)b*C1 + c)*Hc*Wc + (size_t)(y>>1)*Wc + (x>>1)];
        if (upm) v *= upm[(size_t)b*Hc*Wc + (size_t)(y>>1)*Wc + (x>>1)];
    } else {
        v = skip[((size_t)b*C2 + (c-C1))*Hf*Wf + (size_t)y*Wf + x];
    }
    if (cam) v *= cam[(size_t)b*Hf*Wf + (size_t)y*Wf + x];
    out[idx] = packf(v);
}

// ---------------- HMMA implicit-GEMM conv, K-chunk 64, reordered K ----------------
#define ROWB 144
#define S_AH 0
#define S_AL 18432
#define S_BH 36864
#define S_BL 55296
#define CONV_SMEM 73728

template<int PAD>  // 1 reflect, 2 edge
__global__ __launch_bounds__(256)
void conv_hmma(const __nv_bfloat16* __restrict__ Ah, const __nv_bfloat16* __restrict__ Al,
               const uint32_t* __restrict__ pin, float* __restrict__ out,
               int IC, int ICpad, int OC, int H, int W, int Kpad, int S)
{
    extern __shared__ __align__(16) unsigned char sm[];
    const uint32_t sb = smem_u32(sm);
    const int tid = threadIdx.x, wid = tid >> 5, lane = tid & 31;
    const int HW = H * W;
    const int n0 = blockIdx.x * 128;
    const int Mtiles = gridDim.y / S;
    const int mt_id = blockIdx.y % Mtiles, ks = blockIdx.y / Mtiles;
    const int m0 = mt_id * 128;
    const int b = blockIdx.z;

    const int chunks = Kpad >> 6;
    const int cseg = (chunks + S - 1) / S;
    const int c0 = ks * cseg, c1 = min(chunks, c0 + cseg);

    const uint32_t* inb = pin + (size_t)b * IC * HW;
    const int wm = (wid >> 2) * 64, wn = (wid & 3) * 32;

    float acc[4][4][4];
    #pragma unroll
    for (int i=0;i<4;i++) for (int j=0;j<4;j++) for (int k=0;k<4;k++) acc[i][j][k]=0.f;

    const int mloc = tid >> 1, kh = tid & 1;
    const int nglob = n0 + mloc;
    const bool okpix = (nglob < HW);
    const int py = okpix ? nglob / W : 0;
    const int px_ = okpix ? nglob - py*W : 0;

    // thread's k start, tap index t and channel offset (K reordered: k = t*ICpad + ic)
    int kthr = (c0 << 6) + kh*32;
    int tap = kthr / ICpad;
    int icr = kthr - tap*ICpad;

    for (int c = c0; c < c1; ++c) {
        const int kc = c << 6;
        // ---- A: weights hi/lo, each thread 32 bf16 (64B) per plane ----
        {
            const uint4* qH = (const uint4*)(Ah + (size_t)(m0+mloc)*Kpad + kc + kh*32);
            const uint4* qL = (const uint4*)(Al + (size_t)(m0+mloc)*Kpad + kc + kh*32);
            int d = mloc*ROWB + kh*64;
            #pragma unroll
            for (int i = 0; i < 4; ++i) {
                *(uint4*)(sm + d + S_AH + i*16) = qH[i];
                *(uint4*)(sm + d + S_AL + i*16) = qL[i];
            }
        }
        // ---- B: gather 32 consecutive channels at fixed tap ----
        {
            int t3 = (tap*11) >> 5;            // tap/3 for tap in 0..8
            int dy = t3 - 1, dx = tap - t3*3 - 1;
            int yy = py + dy, xx = px_ + dx;
            if (PAD == 1) {
                yy = yy<0 ? -yy : (yy>=H ? 2*H-2-yy : yy);
                xx = xx<0 ? -xx : (xx>=W ? 2*W-2-xx : xx);
            } else {
                yy = min(max(yy,0),H-1); xx = min(max(xx,0),W-1);
            }
            const uint32_t* p = inb + (size_t)icr*HW + yy*W + xx;
            int d = mloc*ROWB + kh*64;
            #pragma unroll
            for (int g8 = 0; g8 < 4; ++g8) {
                uint32_t v[8];
                #pragma unroll
                for (int e = 0; e < 8; ++e) {
                    int ic = icr + g8*8 + e;
                    v[e] = (okpix && ic < IC) ? __ldg(p + (size_t)(g8*8+e)*HW) : 0u;
                }
                uint32_t hp0 = __byte_perm(v[0],v[1],0x5410), hp1 = __byte_perm(v[2],v[3],0x5410);
                uint32_t hp2 = __byte_perm(v[4],v[5],0x5410), hp3 = __byte_perm(v[6],v[7],0x5410);
                uint32_t lp0 = __byte_perm(v[0],v[1],0x7632), lp1 = __byte_perm(v[2],v[3],0x7632);
                uint32_t lp2 = __byte_perm(v[4],v[5],0x7632), lp3 = __byte_perm(v[6],v[7],0x7632);
                *(uint4*)(sm + d + S_BH + g8*16) = make_uint4(hp0,hp1,hp2,hp3);
                *(uint4*)(sm + d + S_BL + g8*16) = make_uint4(lp0,lp1,lp2,lp3);
            }
        }
        // advance tap/channel tracker by 64 k
        icr += 64;
        if (icr >= ICpad) { icr -= ICpad; ++tap; }
        __syncthreads();
        // ---- compute: 4 k16 steps ----
        #pragma unroll
        for (int kk = 0; kk < 4; ++kk) {
            uint32_t bh[4][2], bl[4][2];
            #pragma unroll
            for (int nt2 = 0; nt2 < 2; ++nt2) {
                int g = lane >> 3;
                int brow = wn + nt2*16 + (lane & 7) + ((g & 2) ? 8 : 0);
                uint32_t baddr = sb + brow*ROWB + kk*32 + ((g & 1) ? 16 : 0);
                ldsm4(bh[nt2*2][0], bh[nt2*2][1], bh[nt2*2+1][0], bh[nt2*2+1][1], baddr + S_BH);
                ldsm4(bl[nt2*2][0], bl[nt2*2][1], bl[nt2*2+1][0], bl[nt2*2+1][1], baddr + S_BL);
            }
            #pragma unroll
            for (int mt = 0; mt < 4; ++mt) {
                int arow = wm + mt*16 + (lane & 15);
                uint32_t aaddr = sb + arow*ROWB + kk*32 + ((lane >> 4) ? 16 : 0);
                uint32_t ah[4], al[4];
                ldsm4(ah[0], ah[1], ah[2], ah[3], aaddr + S_AH);
                ldsm4(al[0], al[1], al[2], al[3], aaddr + S_AL);
                #pragma unroll
                for (int nt = 0; nt < 4; ++nt) {
                    mma16816(acc[mt][nt], ah, bh[nt]);
                    mma16816(acc[mt][nt], ah, bl[nt]);
                    mma16816(acc[mt][nt], al, bh[nt]);
                }
            }
        }
        __syncthreads();
    }

    // ---- epilogue ----
    float* ob = out + (size_t)b * OC * HW;
    const bool direct = (S == 1);
    #pragma unroll
    for (int mt = 0; mt < 4; ++mt) {
        #pragma unroll
        for (int nt = 0; nt < 4; ++nt) {
            #pragma unroll
            for (int cr = 0; cr < 4; ++cr) {
                int r = wm + mt*16 + (lane >> 2) + ((cr >= 2) ? 8 : 0);
                int col = wn + nt*8 + (lane & 3)*2 + (cr & 1);
                int oc = m0 + r, px = n0 + col;
                if (oc < OC && px < HW) {
                    float v = acc[mt][nt][cr];
                    if (direct) ob[(size_t)oc*HW + px] = v;
                    else atomicAdd(ob + (size_t)oc*HW + px, v);
                }
            }
        }
    }
}

// ---------------- finalize big: buf = leaky(buf+bias) * mask ----------------
__global__ void finalize_big(float* __restrict__ buf, const float* __restrict__ bias,
                             const float* __restrict__ mask, int C, int HW, int leaky, int total)
{
    int i = blockIdx.x*256 + threadIdx.x;
    if (i >= total) return;
    int p = i % HW, t = i / HW, c = t % C, b = t / C;
    float v = buf[i] + bias[c];
    if (leaky) v = v > 0.f ? v : 0.2f*v;
    if (mask) v *= mask[(size_t)b*HW + p];
    buf[i] = v;
}

// ---------------- small conv partial (IC-split, atomic) ----------------
template<int NOUT, int PAD>
__global__ void conv_small_part(const float* __restrict__ in, const float* __restrict__ wgt,
                                float* __restrict__ acc, int IC, int nsp, int H, int W)
{
    int b = blockIdx.z, sp = blockIdx.y;
    int HW = H*W;
    int p = blockIdx.x*128 + threadIdx.x;
    if (p >= HW) return;
    int y = p / W, x = p - y*W;
    int icPer = (IC + nsp - 1)/nsp, ic0 = sp*icPer, ic1 = min(IC, ic0+icPer);
    float a[NOUT];
    #pragma unroll
    for (int j = 0; j < NOUT; ++j) a[j] = 0.f;
    const float* inb = in + (size_t)b*IC*HW;
    for (int ic = ic0; ic < ic1; ++ic) {
        const float* ip = inb + (size_t)ic*HW;
        const float* wp = wgt + (size_t)ic*9;
        #pragma unroll
        for (int t = 0; t < 9; ++t) {
            int yy = y + t/3 - 1, xx = x + t%3 - 1;
            float v;
            if (PAD == 0) v = (yy>=0 && yy<H && xx>=0 && xx<W) ? __ldg(ip + yy*W + xx) : 0.f;
            else { yy = min(max(yy,0),H-1); xx = min(max(xx,0),W-1); v = __ldg(ip + yy*W + xx); }
            #pragma unroll
            for (int j = 0; j < NOUT; ++j)
                a[j] = fmaf(v, __ldg(wp + (size_t)j*IC*9 + t), a[j]);
        }
    }
    #pragma unroll
    for (int j = 0; j < NOUT; ++j)
        atomicAdd(acc + ((size_t)b*NOUT + j)*HW + p, a[j]);
}

__global__ void finalize_small(float* __restrict__ buf, const float* __restrict__ bias,
                               const float* __restrict__ mask, int NOUT, int H, int W,
                               float scale, int total)
{
    int i = blockIdx.x*256 + threadIdx.x;
    if (i >= total) return;
    int HW = H*W;
    int p = i % HW, t = i / HW, c = t % NOUT, b = t / NOUT;
    float v = (buf[i] + bias[c]) * scale;
    if (mask) {
        int y = p / W, x = p - y*W;
        v *= mask[(size_t)b*(HW/4) + (y>>1)*(W>>1) + (x>>1)];
    }
    buf[i] = v;
}

// ---------------- glue ----------------
__global__ void idwt_k(const float* __restrict__ ll, const float* __restrict__ h,
                       float* __restrict__ out, int Hc, int Wc)
{
    int b = blockIdx.z;
    int p = blockIdx.x*256 + threadIdx.x;
    if (p >= Hc*Wc) return;
    int y = p / Wc, x = p - y*Wc;
    float l = ll[(size_t)b*Hc*Wc + p];
    const float* hb = h + (size_t)b*3*Hc*Wc;
    float lh = hb[p], hl = hb[Hc*Wc+p], hh = hb[2*Hc*Wc+p];
    float a = (l+lh)*0.5f, c2 = (l-lh)*0.5f, d2 = (hl+hh)*0.5f, e = (hl-hh)*0.5f;
    float* ob = out + (size_t)b*(2*Hc)*(2*Wc);
    int W2 = 2*Wc;
    ob[(size_t)(2*y)*W2 + 2*x]     = a + d2;
    ob[(size_t)(2*y)*W2 + 2*x+1]   = c2 + e;
    ob[(size_t)(2*y+1)*W2 + 2*x]   = a - d2;
    ob[(size_t)(2*y+1)*W2 + 2*x+1] = c2 - e;
}
__global__ void minmax_k(const float* __restrict__ d, int n, float* __restrict__ thr)
{
    __shared__ float smn[1024], smx[1024];
    int tid = threadIdx.x;
    float mn = 3.4e38f, mx = -3.4e38f;
    for (int i = tid; i < n; i += 1024) { float v = d[i]; mn = fminf(mn,v); mx = fmaxf(mx,v); }
    smn[tid]=mn; smx[tid]=mx; __syncthreads();
    for (int s=512; s>0; s>>=1) {
        if (tid<s){ smn[tid]=fminf(smn[tid],smn[tid+s]); smx[tid]=fmaxf(smx[tid],smx[tid+s]); }
        __syncthreads();
    }
    if (tid==0) thr[0] = (smx[0]-smn[0])*0.1f;
}
__global__ void mask_k(const float* __restrict__ h, const float* __restrict__ thr,
                       float* __restrict__ mask, int Hc, int Wc)
{
    int b = blockIdx.z;
    int p = blockIdx.x*256 + threadIdx.x;
    if (p >= Hc*Wc) return;
    const float* hb = h + (size_t)b*3*Hc*Wc;
    float m = fmaxf(fabsf(hb[p]), fmaxf(fabsf(hb[Hc*Wc+p]), fabsf(hb[2*Hc*Wc+p])));
    mask[(size_t)b*Hc*Wc + p] = (m > thr[0]) ? 1.f : 0.f;
}
__global__ void pool_coarse_k(const float* __restrict__ mask, float* __restrict__ upm, int Hc, int Wc)
{
    int b = blockIdx.z;
    int p = blockIdx.x*256 + threadIdx.x;
    if (p >= Hc*Wc) return;
    int y = p / Wc, x = p - y*Wc;
    const float* mb = mask + (size_t)b*Hc*Wc;
    float r = 0.f;
    for (int dy=-2;dy<=2;dy++){ int yy=y+dy; if (yy<0||yy>=Hc) continue;
      for (int dx=-2;dx<=2;dx++){ int xx=x+dx; if (xx<0||xx>=Wc) continue;
        r = fmaxf(r, mb[yy*Wc+xx]); } }
    upm[(size_t)b*Hc*Wc + p] = (r > 0.f) ? 1.f : 0.f;
}
__global__ void pool_fine_k(const float* __restrict__ mask, float* __restrict__ cam,
                            float* __restrict__ wm, int Hc, int Wc)
{
    int b = blockIdx.z;
    int Hf = 2*Hc, Wf = 2*Wc;
    int p = blockIdx.x*256 + threadIdx.x;
    if (p >= Hf*Wf) return;
    int y = p / Wf, x = p - y*Wf;
    const float* mb = mask + (size_t)b*Hc*Wc;
    float c5 = 0.f, c3 = 0.f;
    for (int dy=-2;dy<=2;dy++){ int fy=y+dy; if (fy<0||fy>=Hf) continue;
      for (int dx=-2;dx<=2;dx++){ int fx=x+dx; if (fx<0||fx>=Wf) continue;
        float v = mb[(fy>>1)*Wc + (fx>>1)];
        c5 = fmaxf(c5, v);
        if (dy>=-1 && dy<=1 && dx>=-1 && dx<=1) c3 = fmaxf(c3, v);
      } }
    cam[(size_t)b*Hf*Wf + p] = (c5 > 0.f) ? 1.f : 0.f;
    wm [(size_t)b*Hf*Wf + p] = (c3 > 0.f) ? 1.f : 0.f;
}

// =======================================================================
extern "C" void kernel_launch(void* const* d_in, const int* in_sizes, int n_in,
                              void* d_out, int out_size)
{
    const float* x32 = (const float*)d_in[0];
    const float* x16 = (const float*)d_in[1];
    const float* x8  = (const float*)d_in[2];
    const float* x4  = (const float*)d_in[3];
    const float* c2w = (const float*)d_in[4];  const float* c2b = (const float*)d_in[5];
    const float* u1w = (const float*)d_in[6];  const float* u1b = (const float*)d_in[7];
    const float* wllw= (const float*)d_in[8];  const float* wllb= (const float*)d_in[9];
    const float* w1w = (const float*)d_in[10]; const float* w1b = (const float*)d_in[11];
    const float* u2w = (const float*)d_in[12]; const float* u2b = (const float*)d_in[13];
    const float* w2w = (const float*)d_in[14]; const float* w2b = (const float*)d_in[15];
    const float* u3w = (const float*)d_in[16]; const float* u3b = (const float*)d_in[17];
    const float* w3w = (const float*)d_in[18]; const float* w3b = (const float*)d_in[19];

    float *xd0,*xd1,*ll1,*h1,*ll40,*mask1,*upm1,*cam1,*wm1;
    float *xa,*h2,*ll80,*mask2,*upm2,*cam2,*wm2,*xb,*h3,*thr;
    uint32_t *px32,*cat1,*feat1,*feat0;
    __nv_bfloat16 *w2h,*w2l,*p1h,*p1l,*p2h,*p2l,*p3h,*p3l;
    cudaGetSymbolAddress((void**)&xd0,g_xd0);   cudaGetSymbolAddress((void**)&xd1,g_xd1);
    cudaGetSymbolAddress((void**)&ll1,g_ll1);   cudaGetSymbolAddress((void**)&h1,g_h1);
    cudaGetSymbolAddress((void**)&ll40,g_ll40); cudaGetSymbolAddress((void**)&mask1,g_mask1);
    cudaGetSymbolAddress((void**)&upm1,g_upm1); cudaGetSymbolAddress((void**)&cam1,g_cam1);
    cudaGetSymbolAddress((void**)&wm1,g_wm1);   cudaGetSymbolAddress((void**)&xa,g_xa);
    cudaGetSymbolAddress((void**)&h2,g_h2);     cudaGetSymbolAddress((void**)&ll80,g_ll80);
    cudaGetSymbolAddress((void**)&mask2,g_mask2); cudaGetSymbolAddress((void**)&upm2,g_upm2);
    cudaGetSymbolAddress((void**)&cam2,g_cam2); cudaGetSymbolAddress((void**)&wm2,g_wm2);
    cudaGetSymbolAddress((void**)&xb,g_xb);     cudaGetSymbolAddress((void**)&h3,g_h3);
    cudaGetSymbolAddress((void**)&thr,g_thr);
    cudaGetSymbolAddress((void**)&px32,g_px32); cudaGetSymbolAddress((void**)&cat1,g_cat1);
    cudaGetSymbolAddress((void**)&feat1,g_feat1); cudaGetSymbolAddress((void**)&feat0,g_feat0);
    cudaGetSymbolAddress((void**)&w2h,g_w2h);   cudaGetSymbolAddress((void**)&w2l,g_w2l);
    cudaGetSymbolAddress((void**)&p1h,g_u1h);   cudaGetSymbolAddress((void**)&p1l,g_u1l);
    cudaGetSymbolAddress((void**)&p2h,g_u2h);   cudaGetSymbolAddress((void**)&p2l,g_u2l);
    cudaGetSymbolAddress((void**)&p3h,g_u3h);   cudaGetSymbolAddress((void**)&p3l,g_u3l);

    cudaFuncSetAttribute(conv_hmma<1>, cudaFuncAttributeMaxDynamicSharedMemorySize, CONV_SMEM);
    cudaFuncSetAttribute(conv_hmma<2>, cudaFuncAttributeMaxDynamicSharedMemorySize, CONV_SMEM);

    // pack weights (K reordered). ICpad: 2240,1536,768,384 ; Kpad: 20160,13824,6912,3456
    { int t=1152*2240; pack_w_k<<<dim3((t+255)/256,9),256>>>(c2w, w2h, w2l, 1104, 2208, 2240, 20160, t); }
    { int t=640*1536;  pack_w_k<<<dim3((t+255)/256,9),256>>>(u1w, p1h, p1l, 552, 1488, 1536, 13824, t); }
    { int t=384*768;   pack_w_k<<<dim3((t+255)/256,9),256>>>(u2w, p2h, p2l, 276, 744, 768, 6912, t); }
    { int t=256*384;   pack_w_k<<<dim3((t+255)/256,9),256>>>(u3w, p3h, p3l, 138, 372, 384, 3456, t); }

    // pack conv2 input
    { int t=BATCH*2208*320; pack_x_k<<<(t+255)/256,256>>>(x32, px32, t); }

    // zero atomic accumulators
    cudaMemsetAsync(xd0, 0, sizeof(g_xd0), 0);
    cudaMemsetAsync(xd1, 0, sizeof(g_xd1), 0);
    cudaMemsetAsync(ll1, 0, sizeof(g_ll1), 0);
    cudaMemsetAsync(h1,  0, sizeof(g_h1), 0);
    cudaMemsetAsync(h2,  0, sizeof(g_h2), 0);
    cudaMemsetAsync(h3,  0, sizeof(g_h3), 0);

    // conv2 (edge): 2208->1104, 10x32, Mtiles=9, Ntiles=3, S=4
    conv_hmma<2><<<dim3(3, 9*4, BATCH), 256, CONV_SMEM>>>(w2h, w2l, px32, xd0, 2208, 2240, 1104, 10, 32, 20160, 4);
    finalize_big<<<(BATCH*1104*320+255)/256,256>>>(xd0, c2b, nullptr, 1104, 320, 0, BATCH*1104*320);
    // cat1 (packed)
    { int t = BATCH*1488*20*64;
      feat_pack_k<<<(t+255)/256,256>>>(xd0, x16, nullptr, nullptr, cat1, 1104, 384, 20, 64, t); }
    // up1 (reflect): 1488->552, 20x64, Mtiles=5, S=2
    conv_hmma<1><<<dim3(10, 5*2, BATCH), 256, CONV_SMEM>>>(p1h, p1l, cat1, xd1, 1488, 1536, 552, 20, 64, 13824, 2);
    finalize_big<<<(BATCH*552*1280+255)/256,256>>>(xd1, u1b, nullptr, 552, 1280, 1, BATCH*552*1280);
    // wave1ll (edge, x8) / wave1 (zero, x4)
    conv_small_part<1,2><<<dim3(10,12,BATCH),128>>>(xd1, wllw, ll1, 552, 12, 20, 64);
    conv_small_part<3,0><<<dim3(10,12,BATCH),128>>>(xd1, w1w, h1, 552, 12, 20, 64);
    finalize_small<<<(BATCH*1280+255)/256,256>>>(ll1, wllb, nullptr, 1, 20, 64, 8.f, BATCH*1280);
    finalize_small<<<(BATCH*3*1280+255)/256,256>>>(h1, w1b, nullptr, 3, 20, 64, 4.f, BATCH*3*1280);
    idwt_k<<<dim3(5,1,BATCH),256>>>(ll1, h1, ll40, 20, 64);
    minmax_k<<<1,1024>>>(ll40, BATCH*40*128, thr);
    mask_k<<<dim3(5,1,BATCH),256>>>(h1, thr, mask1, 20, 64);
    pool_coarse_k<<<dim3(5,1,BATCH),256>>>(mask1, upm1, 20, 64);
    pool_fine_k<<<dim3(20,1,BATCH),256>>>(mask1, cam1, wm1, 20, 64);
    // feat1 (packed) + up2 (reflect): 744->276, 40x128, Mtiles=3, S=1
    { int t = BATCH*744*40*128;
      feat_pack_k<<<(t+255)/256,256>>>(xd1, x8, upm1, cam1, feat1, 552, 192, 40, 128, t); }
    conv_hmma<1><<<dim3(40, 3, BATCH), 256, CONV_SMEM>>>(p2h, p2l, feat1, xa, 744, 768, 276, 40, 128, 6912, 1);
    finalize_big<<<(BATCH*276*5120+255)/256,256>>>(xa, u2b, wm1, 276, 5120, 1, BATCH*276*5120);
    // h2
    conv_small_part<3,0><<<dim3(40,8,BATCH),128>>>(xa, w2w, h2, 276, 8, 40, 128);
    finalize_small<<<(BATCH*3*5120+255)/256,256>>>(h2, w2b, mask1, 3, 40, 128, 2.f, BATCH*3*5120);
    idwt_k<<<dim3(20,1,BATCH),256>>>(ll40, h2, ll80, 40, 128);
    minmax_k<<<1,1024>>>(ll80, BATCH*80*256, thr);
    mask_k<<<dim3(20,1,BATCH),256>>>(h2, thr, mask2, 40, 128);
    pool_coarse_k<<<dim3(20,1,BATCH),256>>>(mask2, upm2, 40, 128);
    pool_fine_k<<<dim3(80,1,BATCH),256>>>(mask2, cam2, wm2, 40, 128);
    // feat0 (packed) + up3 (reflect): 372->138, 80x256, Mtiles=2, S=1
    { int t = BATCH*372*80*256;
      feat_pack_k<<<(t+255)/256,256>>>(xa, x4, upm2, cam2, feat0, 276, 96, 80, 256, t); }
    conv_hmma<1><<<dim3(160, 2, BATCH), 256, CONV_SMEM>>>(p3h, p3l, feat0, xb, 372, 384, 138, 80, 256, 3456, 1);
    finalize_big<<<(BATCH*138*20480+255)/256,256>>>(xb, u3b, wm2, 138, 20480, 1, BATCH*138*20480);
    // h3
    conv_small_part<3,0><<<dim3(160,4,BATCH),128>>>(xb, w3w, h3, 138, 4, 80, 256);
    finalize_small<<<(BATCH*3*20480+255)/256,256>>>(h3, w3b, mask2, 3, 80, 256, 1.f, BATCH*3*20480);
    idwt_k<<<dim3(80,1,BATCH),256>>>(ll80, h3, (float*)d_out, 80, 256);
}

// round 7
// speedup vs baseline: 2.7441x; 1.2891x over previous
#include <cuda_runtime.h>
#include <cuda_bf16.h>
#include <math.h>
#include <stdint.h>

#define BATCH 4

__device__ __forceinline__ uint32_t smem_u32(const void* p){
    uint32_t a; asm("{ .reg .u64 t; cvta.to.shared.u64 t, %1; cvt.u32.u64 %0, t; }":"=r"(a):"l"(p)); return a;
}
__device__ __forceinline__ void ldsm4(uint32_t& r0, uint32_t& r1, uint32_t& r2, uint32_t& r3, uint32_t a){
    asm volatile("ldmatrix.sync.aligned.m8n8.x4.shared.b16 {%0,%1,%2,%3}, [%4];"
        :"=r"(r0),"=r"(r1),"=r"(r2),"=r"(r3):"r"(a));
}
__device__ __forceinline__ void mma16816(float* c, const uint32_t* a, const uint32_t* b){
    asm volatile("mma.sync.aligned.m16n8k16.row.col.f32.bf16.bf16.f32 "
        "{%0,%1,%2,%3}, {%4,%5,%6,%7}, {%8,%9}, {%0,%1,%2,%3};"
        : "+f"(c[0]),"+f"(c[1]),"+f"(c[2]),"+f"(c[3])
        : "r"(a[0]),"r"(a[1]),"r"(a[2]),"r"(a[3]),"r"(b[0]),"r"(b[1]));
}
__device__ __forceinline__ void cpasync16(uint32_t saddr, const void* g){
    asm volatile("cp.async.cg.shared.global [%0], [%1], 16;"::"r"(saddr),"l"(g));
}
__device__ __forceinline__ void cpcommit(){ asm volatile("cp.async.commit_group;"); }
__device__ __forceinline__ void cpwait0(){ asm volatile("cp.async.wait_group 0;"); }
__device__ __forceinline__ uint32_t packf(float v){
    __nv_bfloat16 h = __float2bfloat16(v);
    __nv_bfloat16 l = __float2bfloat16(v - __bfloat162float(h));
    return (uint32_t)*(unsigned short*)&h | ((uint32_t)*(unsigned short*)&l << 16);
}

// ---------------- scratch ----------------
__device__ float g_xd0[BATCH*1104*10*32];
__device__ float g_xd1[BATCH*552*20*64];
__device__ float g_ll1[BATCH*20*64];
__device__ float g_h1[BATCH*3*20*64];
__device__ float g_ll40[BATCH*40*128];
__device__ float g_mask1[BATCH*20*64];
__device__ float g_upm1[BATCH*20*64];
__device__ float g_cam1[BATCH*40*128];
__device__ float g_wm1[BATCH*40*128];
__device__ float g_xa[BATCH*276*40*128];
__device__ float g_h2[BATCH*3*40*128];
__device__ float g_ll80[BATCH*80*256];
__device__ float g_mask2[BATCH*40*128];
__device__ float g_upm2[BATCH*40*128];
__device__ float g_cam2[BATCH*80*256];
__device__ float g_wm2[BATCH*80*256];
__device__ float g_xb[BATCH*138*80*256];
__device__ float g_h3[BATCH*3*80*256];
__device__ float g_thr[1];
// packed u32 (bf16 hi | lo<<16) conv inputs
__device__ __align__(16) uint32_t g_px32[BATCH*2208*10*32];
__device__ __align__(16) uint32_t g_cat1[BATCH*1488*20*64];
__device__ __align__(16) uint32_t g_feat1[BATCH*744*40*128];
__device__ __align__(16) uint32_t g_feat0[BATCH*372*80*256];
// packed weights (hi/lo planes), K reordered as t*ICpad+ic
__device__ __align__(16) __nv_bfloat16 g_w2h[1152*20160];
__device__ __align__(16) __nv_bfloat16 g_w2l[1152*20160];
__device__ __align__(16) __nv_bfloat16 g_u1h[640*13824];
__device__ __align__(16) __nv_bfloat16 g_u1l[640*13824];
__device__ __align__(16) __nv_bfloat16 g_u2h[384*6912];
__device__ __align__(16) __nv_bfloat16 g_u2l[384*6912];
__device__ __align__(16) __nv_bfloat16 g_u3h[256*3456];
__device__ __align__(16) __nv_bfloat16 g_u3l[256*3456];

// ---------------- weight pack: w[oc, ic*9+t] -> planes[ocpad, t*ICpad+ic] ----------------
__global__ void pack_w_k(const float* __restrict__ w, __nv_bfloat16* __restrict__ hi,
                         __nv_bfloat16* __restrict__ lo, int OC, int IC, int ICpad, int Kpad, int totRC)
{
    int i = blockIdx.x*256 + threadIdx.x;
    if (i >= totRC) return;
    int t = blockIdx.y;
    int r = i / ICpad, ic = i - r*ICpad;
    float v = (r < OC && ic < IC) ? w[(size_t)r*IC*9 + ic*9 + t] : 0.f;
    __nv_bfloat16 h = __float2bfloat16(v);
    size_t o = (size_t)r*Kpad + t*ICpad + ic;
    hi[o] = h;
    lo[o] = __float2bfloat16(v - __bfloat162float(h));
}

// ---------------- input pack ----------------
__global__ void pack_x_k(const float* __restrict__ x, uint32_t* __restrict__ o, int total)
{
    int i = blockIdx.x*256 + threadIdx.x;
    if (i < total) o[i] = packf(x[i]);
}

// ---------------- feat build + pack ----------------
__global__ void feat_pack_k(const float* __restrict__ xc, const float* __restrict__ skip,
                            const float* __restrict__ upm, const float* __restrict__ cam,
                            uint32_t* __restrict__ out, int C1, int C2, int Hf, int Wf, int total)
{
    int idx = blockIdx.x*256 + threadIdx.x;
    if (idx >= total) return;
    int Wc = Wf >> 1, Hc = Hf >> 1;
    int x = idx % Wf; int t = idx / Wf;
    int y = t % Hf;  t /= Hf;
    int c = t % (C1+C2); int b = t / (C1+C2);
    float v;
    if (c < C1) {
        v = xc[((size_t)b*C1 + c)*Hc*Wc + (size_t)(y>>1)*Wc + (x>>1)];
        if (upm) v *= upm[(size_t)b*Hc*Wc + (size_t)(y>>1)*Wc + (x>>1)];
    } else {
        v = skip[((size_t)b*C2 + (c-C1))*Hf*Wf + (size_t)y*Wf + x];
    }
    if (cam) v *= cam[(size_t)b*Hf*Wf + (size_t)y*Wf + x];
    out[idx] = packf(v);
}

// ---------------- HMMA implicit-GEMM conv: pipelined, double-buffered ----------------
#define ROWB 144
#define S_AH 0
#define S_AL 18432
#define S_BH 36864
#define S_BL 55296
#define BUFSZ 73728
#define CONV_SMEM (2*BUFSZ)

template<int PAD, int MT>  // PAD: 1 reflect, 2 edge. M-tile = 32*MT rows.
__global__ __launch_bounds__(256)
void conv_hmma(const __nv_bfloat16* __restrict__ Ah, const __nv_bfloat16* __restrict__ Al,
               const uint32_t* __restrict__ pin, float* __restrict__ out,
               int IC, int ICpad, int OC, int H, int W, int Kpad, int S,
               const float* __restrict__ bias, const float* __restrict__ mask, int leaky)
{
    extern __shared__ __align__(16) unsigned char sm[];
    const uint32_t sb = smem_u32(sm);
    const int tid = threadIdx.x, wid = tid >> 5, lane = tid & 31;
    const int HW = H * W;
    const int n0 = blockIdx.x * 128;
    const int Mtiles = gridDim.y / S;
    const int mt_id = blockIdx.y % Mtiles, ks = blockIdx.y / Mtiles;
    const int m0 = mt_id * (32*MT);
    const int b = blockIdx.z;

    const int chunks = Kpad >> 6;
    const int cseg = (chunks + S - 1) / S;
    const int c0 = ks * cseg, c1 = min(chunks, c0 + cseg);

    const uint32_t* inb = pin + (size_t)b * IC * HW;
    const int wm = (wid >> 2) * (16*MT), wn = (wid & 3) * 32;

    float acc[MT][4][4];
    #pragma unroll
    for (int i=0;i<MT;i++) for (int j=0;j<4;j++) for (int k=0;k<4;k++) acc[i][j][k]=0.f;

    const int mloc = tid >> 1, kh = tid & 1;
    const int nglob = n0 + mloc;
    const bool okpix = (nglob < HW);
    const int py = okpix ? nglob / W : 0;
    const int px_ = okpix ? nglob - py*W : 0;

    // tracker for NEXT chunk to gather (K reordered: k = t*ICpad + ic)
    int kthr = (c0 << 6) + kh*32;
    int tap = kthr / ICpad;
    int icr = kthr - tap*ICpad;

    uint32_t bv[32];

    // ---- helpers as lambdas ----
    auto issueA = [&](int c, int bo){
        const int kc = c << 6;
        #pragma unroll
        for (int i = 0; i < MT*2; ++i) {
            int flat = i*256 + tid;
            int fo = flat * 16;
            int plane = fo / (32*MT*128);
            int rem = fo - plane*(32*MT*128);
            int row = rem >> 7, col = rem & 127;
            const __nv_bfloat16* src = (plane ? Al : Ah) + (size_t)(m0+row)*Kpad + kc + (col>>1);
            cpasync16(sb + bo + (plane ? S_AL : S_AH) + row*ROWB + col, src);
        }
        cpcommit();
    };
    auto gatherB = [&](){
        int t3 = (tap*11) >> 5;
        int dy = t3 - 1, dx = tap - t3*3 - 1;
        int yy = py + dy, xx = px_ + dx;
        if (PAD == 1) {
            yy = yy<0 ? -yy : (yy>=H ? 2*H-2-yy : yy);
            xx = xx<0 ? -xx : (xx>=W ? 2*W-2-xx : xx);
        } else {
            yy = min(max(yy,0),H-1); xx = min(max(xx,0),W-1);
        }
        const uint32_t* p = inb + (size_t)icr*HW + yy*W + xx;
        #pragma unroll
        for (int e = 0; e < 32; ++e)
            bv[e] = (okpix && (icr + e) < IC) ? __ldg(p + (size_t)e*HW) : 0u;
        icr += 64;
        if (icr >= ICpad) { icr -= ICpad; ++tap; }
    };
    auto stsB = [&](int bo){
        int d = mloc*ROWB + kh*64;
        #pragma unroll
        for (int g8 = 0; g8 < 4; ++g8) {
            uint32_t* v = bv + g8*8;
            uint32_t hp0 = __byte_perm(v[0],v[1],0x5410), hp1 = __byte_perm(v[2],v[3],0x5410);
            uint32_t hp2 = __byte_perm(v[4],v[5],0x5410), hp3 = __byte_perm(v[6],v[7],0x5410);
            uint32_t lp0 = __byte_perm(v[0],v[1],0x7632), lp1 = __byte_perm(v[2],v[3],0x7632);
            uint32_t lp2 = __byte_perm(v[4],v[5],0x7632), lp3 = __byte_perm(v[6],v[7],0x7632);
            *(uint4*)(sm + bo + d + S_BH + g8*16) = make_uint4(hp0,hp1,hp2,hp3);
            *(uint4*)(sm + bo + d + S_BL + g8*16) = make_uint4(lp0,lp1,lp2,lp3);
        }
    };

    // ---- prologue ----
    issueA(c0, 0);
    gatherB();

    for (int c = c0; c < c1; ++c) {
        const int bo = ((c - c0) & 1) * BUFSZ;
        const int bn = BUFSZ - bo;
        cpwait0();           // A(c) resident
        stsB(bo);            // B(c) regs -> smem
        __syncthreads();
        if (c + 1 < c1) {
            issueA(c + 1, bn);   // prefetch A(c+1)
            gatherB();           // prefetch B(c+1) -> regs (latency overlapped with MMA)
        }
        // ---- compute on buffer bo ----
        #pragma unroll
        for (int kk = 0; kk < 4; ++kk) {
            uint32_t bh[4][2], bl[4][2];
            #pragma unroll
            for (int nt2 = 0; nt2 < 2; ++nt2) {
                int g = lane >> 3;
                int brow = wn + nt2*16 + (lane & 7) + ((g & 2) ? 8 : 0);
                uint32_t baddr = sb + bo + brow*ROWB + kk*32 + ((g & 1) ? 16 : 0);
                ldsm4(bh[nt2*2][0], bh[nt2*2][1], bh[nt2*2+1][0], bh[nt2*2+1][1], baddr + S_BH);
                ldsm4(bl[nt2*2][0], bl[nt2*2][1], bl[nt2*2+1][0], bl[nt2*2+1][1], baddr + S_BL);
            }
            #pragma unroll
            for (int mt = 0; mt < MT; ++mt) {
                int arow = wm + mt*16 + (lane & 15);
                uint32_t aaddr = sb + bo + arow*ROWB + kk*32 + ((lane >> 4) ? 16 : 0);
                uint32_t ah[4], al[4];
                ldsm4(ah[0], ah[1], ah[2], ah[3], aaddr + S_AH);
                ldsm4(al[0], al[1], al[2], al[3], aaddr + S_AL);
                #pragma unroll
                for (int nt = 0; nt < 4; ++nt) {
                    mma16816(acc[mt][nt], ah, bh[nt]);
                    mma16816(acc[mt][nt], ah, bl[nt]);
                    mma16816(acc[mt][nt], al, bh[nt]);
                }
            }
        }
        __syncthreads();
    }

    // ---- epilogue ----
    float* ob = out + (size_t)b * OC * HW;
    const float* mb = mask ? mask + (size_t)b*HW : nullptr;
    const bool direct = (S == 1);
    #pragma unroll
    for (int mt = 0; mt < MT; ++mt) {
        #pragma unroll
        for (int nt = 0; nt < 4; ++nt) {
            #pragma unroll
            for (int cr = 0; cr < 4; ++cr) {
                int r = wm + mt*16 + (lane >> 2) + ((cr >= 2) ? 8 : 0);
                int col = wn + nt*8 + (lane & 3)*2 + (cr & 1);
                int oc = m0 + r, px = n0 + col;
                if (oc < OC && px < HW) {
                    float v = acc[mt][nt][cr];
                    if (direct) {
                        if (bias) v += bias[oc];
                        if (leaky) v = v > 0.f ? v : 0.2f*v;
                        if (mb) v *= mb[px];
                        ob[(size_t)oc*HW + px] = v;
                    } else {
                        atomicAdd(ob + (size_t)oc*HW + px, v);
                    }
                }
            }
        }
    }
}

// ---------------- finalize big ----------------
__global__ void finalize_big(float* __restrict__ buf, const float* __restrict__ bias,
                             const float* __restrict__ mask, int C, int HW, int leaky, int total)
{
    int i = blockIdx.x*256 + threadIdx.x;
    if (i >= total) return;
    int p = i % HW, t = i / HW, c = t % C, b = t / C;
    float v = buf[i] + bias[c];
    if (leaky) v = v > 0.f ? v : 0.2f*v;
    if (mask) v *= mask[(size_t)b*HW + p];
    buf[i] = v;
}

// ---------------- small conv partial ----------------
template<int NOUT, int PAD>
__global__ void conv_small_part(const float* __restrict__ in, const float* __restrict__ wgt,
                                float* __restrict__ acc, int IC, int nsp, int H, int W)
{
    int b = blockIdx.z, sp = blockIdx.y;
    int HW = H*W;
    int p = blockIdx.x*128 + threadIdx.x;
    if (p >= HW) return;
    int y = p / W, x = p - y*W;
    int icPer = (IC + nsp - 1)/nsp, ic0 = sp*icPer, ic1 = min(IC, ic0+icPer);
    float a[NOUT];
    #pragma unroll
    for (int j = 0; j < NOUT; ++j) a[j] = 0.f;
    const float* inb = in + (size_t)b*IC*HW;
    for (int ic = ic0; ic < ic1; ++ic) {
        const float* ip = inb + (size_t)ic*HW;
        const float* wp = wgt + (size_t)ic*9;
        #pragma unroll
        for (int t = 0; t < 9; ++t) {
            int yy = y + t/3 - 1, xx = x + t%3 - 1;
            float v;
            if (PAD == 0) v = (yy>=0 && yy<H && xx>=0 && xx<W) ? __ldg(ip + yy*W + xx) : 0.f;
            else { yy = min(max(yy,0),H-1); xx = min(max(xx,0),W-1); v = __ldg(ip + yy*W + xx); }
            #pragma unroll
            for (int j = 0; j < NOUT; ++j)
                a[j] = fmaf(v, __ldg(wp + (size_t)j*IC*9 + t), a[j]);
        }
    }
    #pragma unroll
    for (int j = 0; j < NOUT; ++j)
        atomicAdd(acc + ((size_t)b*NOUT + j)*HW + p, a[j]);
}

__global__ void finalize_small(float* __restrict__ buf, const float* __restrict__ bias,
                               const float* __restrict__ mask, int NOUT, int H, int W,
                               float scale, int total)
{
    int i = blockIdx.x*256 + threadIdx.x;
    if (i >= total) return;
    int HW = H*W;
    int p = i % HW, t = i / HW, c = t % NOUT, b = t / NOUT;
    float v = (buf[i] + bias[c]) * scale;
    if (mask) {
        int y = p / W, x = p - y*W;
        v *= mask[(size_t)b*(HW/4) + (y>>1)*(W>>1) + (x>>1)];
    }
    buf[i] = v;
}

// ---------------- glue ----------------
__global__ void idwt_k(const float* __restrict__ ll, const float* __restrict__ h,
                       float* __restrict__ out, int Hc, int Wc)
{
    int b = blockIdx.z;
    int p = blockIdx.x*256 + threadIdx.x;
    if (p >= Hc*Wc) return;
    int y = p / Wc, x = p - y*Wc;
    float l = ll[(size_t)b*Hc*Wc + p];
    const float* hb = h + (size_t)b*3*Hc*Wc;
    float lh = hb[p], hl = hb[Hc*Wc+p], hh = hb[2*Hc*Wc+p];
    float a = (l+lh)*0.5f, c2 = (l-lh)*0.5f, d2 = (hl+hh)*0.5f, e = (hl-hh)*0.5f;
    float* ob = out + (size_t)b*(2*Hc)*(2*Wc);
    int W2 = 2*Wc;
    ob[(size_t)(2*y)*W2 + 2*x]     = a + d2;
    ob[(size_t)(2*y)*W2 + 2*x+1]   = c2 + e;
    ob[(size_t)(2*y+1)*W2 + 2*x]   = a - d2;
    ob[(size_t)(2*y+1)*W2 + 2*x+1] = c2 - e;
}
__global__ void minmax_k(const float* __restrict__ d, int n, float* __restrict__ thr)
{
    __shared__ float smn[1024], smx[1024];
    int tid = threadIdx.x;
    float mn = 3.4e38f, mx = -3.4e38f;
    for (int i = tid; i < n; i += 1024) { float v = d[i]; mn = fminf(mn,v); mx = fmaxf(mx,v); }
    smn[tid]=mn; smx[tid]=mx; __syncthreads();
    for (int s=512; s>0; s>>=1) {
        if (tid<s){ smn[tid]=fminf(smn[tid],smn[tid+s]); smx[tid]=fmaxf(smx[tid],smx[tid+s]); }
        __syncthreads();
    }
    if (tid==0) thr[0] = (smx[0]-smn[0])*0.1f;
}
__global__ void mask_k(const float* __restrict__ h, const float* __restrict__ thr,
                       float* __restrict__ mask, int Hc, int Wc)
{
    int b = blockIdx.z;
    int p = blockIdx.x*256 + threadIdx.x;
    if (p >= Hc*Wc) return;
    const float* hb = h + (size_t)b*3*Hc*Wc;
    float m = fmaxf(fabsf(hb[p]), fmaxf(fabsf(hb[Hc*Wc+p]), fabsf(hb[2*Hc*Wc+p])));
    mask[(size_t)b*Hc*Wc + p] = (m > thr[0]) ? 1.f : 0.f;
}
__global__ void pool_coarse_k(const float* __restrict__ mask, float* __restrict__ upm, int Hc, int Wc)
{
    int b = blockIdx.z;
    int p = blockIdx.x*256 + threadIdx.x;
    if (p >= Hc*Wc) return;
    int y = p / Wc, x = p - y*Wc;
    const float* mb = mask + (size_t)b*Hc*Wc;
    float r = 0.f;
    for (int dy=-2;dy<=2;dy++){ int yy=y+dy; if (yy<0||yy>=Hc) continue;
      for (int dx=-2;dx<=2;dx++){ int xx=x+dx; if (xx<0||xx>=Wc) continue;
        r = fmaxf(r, mb[yy*Wc+xx]); } }
    upm[(size_t)b*Hc*Wc + p] = (r > 0.f) ? 1.f : 0.f;
}
__global__ void pool_fine_k(const float* __restrict__ mask, float* __restrict__ cam,
                            float* __restrict__ wm, int Hc, int Wc)
{
    int b = blockIdx.z;
    int Hf = 2*Hc, Wf = 2*Wc;
    int p = blockIdx.x*256 + threadIdx.x;
    if (p >= Hf*Wf) return;
    int y = p / Wf, x = p - y*Wf;
    const float* mb = mask + (size_t)b*Hc*Wc;
    float c5 = 0.f, c3 = 0.f;
    for (int dy=-2;dy<=2;dy++){ int fy=y+dy; if (fy<0||fy>=Hf) continue;
      for (int dx=-2;dx<=2;dx++){ int fx=x+dx; if (fx<0||fx>=Wf) continue;
        float v = mb[(fy>>1)*Wc + (fx>>1)];
        c5 = fmaxf(c5, v);
        if (dy>=-1 && dy<=1 && dx>=-1 && dx<=1) c3 = fmaxf(c3, v);
      } }
    cam[(size_t)b*Hf*Wf + p] = (c5 > 0.f) ? 1.f : 0.f;
    wm [(size_t)b*Hf*Wf + p] = (c3 > 0.f) ? 1.f : 0.f;
}

// =======================================================================
extern "C" void kernel_launch(void* const* d_in, const int* in_sizes, int n_in,
                              void* d_out, int out_size)
{
    const float* x32 = (const float*)d_in[0];
    const float* x16 = (const float*)d_in[1];
    const float* x8  = (const float*)d_in[2];
    const float* x4  = (const float*)d_in[3];
    const float* c2w = (const float*)d_in[4];  const float* c2b = (const float*)d_in[5];
    const float* u1w = (const float*)d_in[6];  const float* u1b = (const float*)d_in[7];
    const float* wllw= (const float*)d_in[8];  const float* wllb= (const float*)d_in[9];
    const float* w1w = (const float*)d_in[10]; const float* w1b = (const float*)d_in[11];
    const float* u2w = (const float*)d_in[12]; const float* u2b = (const float*)d_in[13];
    const float* w2w = (const float*)d_in[14]; const float* w2b = (const float*)d_in[15];
    const float* u3w = (const float*)d_in[16]; const float* u3b = (const float*)d_in[17];
    const float* w3w = (const float*)d_in[18]; const float* w3b = (const float*)d_in[19];

    float *xd0,*xd1,*ll1,*h1,*ll40,*mask1,*upm1,*cam1,*wm1;
    float *xa,*h2,*ll80,*mask2,*upm2,*cam2,*wm2,*xb,*h3,*thr;
    uint32_t *px32,*cat1,*feat1,*feat0;
    __nv_bfloat16 *w2h,*w2l,*p1h,*p1l,*p2h,*p2l,*p3h,*p3l;
    cudaGetSymbolAddress((void**)&xd0,g_xd0);   cudaGetSymbolAddress((void**)&xd1,g_xd1);
    cudaGetSymbolAddress((void**)&ll1,g_ll1);   cudaGetSymbolAddress((void**)&h1,g_h1);
    cudaGetSymbolAddress((void**)&ll40,g_ll40); cudaGetSymbolAddress((void**)&mask1,g_mask1);
    cudaGetSymbolAddress((void**)&upm1,g_upm1); cudaGetSymbolAddress((void**)&cam1,g_cam1);
    cudaGetSymbolAddress((void**)&wm1,g_wm1);   cudaGetSymbolAddress((void**)&xa,g_xa);
    cudaGetSymbolAddress((void**)&h2,g_h2);     cudaGetSymbolAddress((void**)&ll80,g_ll80);
    cudaGetSymbolAddress((void**)&mask2,g_mask2); cudaGetSymbolAddress((void**)&upm2,g_upm2);
    cudaGetSymbolAddress((void**)&cam2,g_cam2); cudaGetSymbolAddress((void**)&wm2,g_wm2);
    cudaGetSymbolAddress((void**)&xb,g_xb);     cudaGetSymbolAddress((void**)&h3,g_h3);
    cudaGetSymbolAddress((void**)&thr,g_thr);
    cudaGetSymbolAddress((void**)&px32,g_px32); cudaGetSymbolAddress((void**)&cat1,g_cat1);
    cudaGetSymbolAddress((void**)&feat1,g_feat1); cudaGetSymbolAddress((void**)&feat0,g_feat0);
    cudaGetSymbolAddress((void**)&w2h,g_w2h);   cudaGetSymbolAddress((void**)&w2l,g_w2l);
    cudaGetSymbolAddress((void**)&p1h,g_u1h);   cudaGetSymbolAddress((void**)&p1l,g_u1l);
    cudaGetSymbolAddress((void**)&p2h,g_u2h);   cudaGetSymbolAddress((void**)&p2l,g_u2l);
    cudaGetSymbolAddress((void**)&p3h,g_u3h);   cudaGetSymbolAddress((void**)&p3l,g_u3l);

    cudaFuncSetAttribute(conv_hmma<1,4>, cudaFuncAttributeMaxDynamicSharedMemorySize, CONV_SMEM);
    cudaFuncSetAttribute(conv_hmma<2,4>, cudaFuncAttributeMaxDynamicSharedMemorySize, CONV_SMEM);
    cudaFuncSetAttribute(conv_hmma<1,2>, cudaFuncAttributeMaxDynamicSharedMemorySize, CONV_SMEM);

    // pack weights. ICpad: 2240,1536,768,384 ; Kpad: 20160,13824,6912,3456
    { int t=1152*2240; pack_w_k<<<dim3((t+255)/256,9),256>>>(c2w, w2h, w2l, 1104, 2208, 2240, 20160, t); }
    { int t=640*1536;  pack_w_k<<<dim3((t+255)/256,9),256>>>(u1w, p1h, p1l, 552, 1488, 1536, 13824, t); }
    { int t=384*768;   pack_w_k<<<dim3((t+255)/256,9),256>>>(u2w, p2h, p2l, 276, 744, 768, 6912, t); }
    { int t=256*384;   pack_w_k<<<dim3((t+255)/256,9),256>>>(u3w, p3h, p3l, 138, 372, 384, 3456, t); }

    { int t=BATCH*2208*320; pack_x_k<<<(t+255)/256,256>>>(x32, px32, t); }

    cudaMemsetAsync(xd0, 0, sizeof(g_xd0), 0);
    cudaMemsetAsync(xd1, 0, sizeof(g_xd1), 0);
    cudaMemsetAsync(ll1, 0, sizeof(g_ll1), 0);
    cudaMemsetAsync(h1,  0, sizeof(g_h1), 0);
    cudaMemsetAsync(h2,  0, sizeof(g_h2), 0);
    cudaMemsetAsync(h3,  0, sizeof(g_h3), 0);

    // conv2 (edge): 2208->1104, 10x32, Mtiles=9, S=4 (atomic + finalize)
    conv_hmma<2,4><<<dim3(3, 9*4, BATCH), 256, CONV_SMEM>>>(w2h, w2l, px32, xd0, 2208, 2240, 1104, 10, 32, 20160, 4, nullptr, nullptr, 0);
    finalize_big<<<(BATCH*1104*320+255)/256,256>>>(xd0, c2b, nullptr, 1104, 320, 0, BATCH*1104*320);
    { int t = BATCH*1488*20*64;
      feat_pack_k<<<(t+255)/256,256>>>(xd0, x16, nullptr, nullptr, cat1, 1104, 384, 20, 64, t); }
    // up1 (reflect): 1488->552, Mtiles=5, S=2 (atomic + finalize w/ leaky)
    conv_hmma<1,4><<<dim3(10, 5*2, BATCH), 256, CONV_SMEM>>>(p1h, p1l, cat1, xd1, 1488, 1536, 552, 20, 64, 13824, 2, nullptr, nullptr, 0);
    finalize_big<<<(BATCH*552*1280+255)/256,256>>>(xd1, u1b, nullptr, 552, 1280, 1, BATCH*552*1280);
    conv_small_part<1,2><<<dim3(10,12,BATCH),128>>>(xd1, wllw, ll1, 552, 12, 20, 64);
    conv_small_part<3,0><<<dim3(10,12,BATCH),128>>>(xd1, w1w, h1, 552, 12, 20, 64);
    finalize_small<<<(BATCH*1280+255)/256,256>>>(ll1, wllb, nullptr, 1, 20, 64, 8.f, BATCH*1280);
    finalize_small<<<(BATCH*3*1280+255)/256,256>>>(h1, w1b, nullptr, 3, 20, 64, 4.f, BATCH*3*1280);
    idwt_k<<<dim3(5,1,BATCH),256>>>(ll1, h1, ll40, 20, 64);
    minmax_k<<<1,1024>>>(ll40, BATCH*40*128, thr);
    mask_k<<<dim3(5,1,BATCH),256>>>(h1, thr, mask1, 20, 64);
    pool_coarse_k<<<dim3(5,1,BATCH),256>>>(mask1, upm1, 20, 64);
    pool_fine_k<<<dim3(20,1,BATCH),256>>>(mask1, cam1, wm1, 20, 64);
    { int t = BATCH*744*40*128;
      feat_pack_k<<<(t+255)/256,256>>>(xd1, x8, upm1, cam1, feat1, 552, 192, 40, 128, t); }
    // up2 (reflect): 744->276, Mtiles=3, S=1, fused epilogue
    conv_hmma<1,4><<<dim3(40, 3, BATCH), 256, CONV_SMEM>>>(p2h, p2l, feat1, xa, 744, 768, 276, 40, 128, 6912, 1, u2b, wm1, 1);
    conv_small_part<3,0><<<dim3(40,8,BATCH),128>>>(xa, w2w, h2, 276, 8, 40, 128);
    finalize_small<<<(BATCH*3*5120+255)/256,256>>>(h2, w2b, mask1, 3, 40, 128, 2.f, BATCH*3*5120);
    idwt_k<<<dim3(20,1,BATCH),256>>>(ll40, h2, ll80, 40, 128);
    minmax_k<<<1,1024>>>(ll80, BATCH*80*256, thr);
    mask_k<<<dim3(20,1,BATCH),256>>>(h2, thr, mask2, 40, 128);
    pool_coarse_k<<<dim3(20,1,BATCH),256>>>(mask2, upm2, 40, 128);
    pool_fine_k<<<dim3(80,1,BATCH),256>>>(mask2, cam2, wm2, 40, 128);
    { int t = BATCH*372*80*256;
      feat_pack_k<<<(t+255)/256,256>>>(xa, x4, upm2, cam2, feat0, 276, 96, 80, 256, t); }
    // up3 (reflect): 372->138, M-tile=64, Mtiles=3, S=1, fused epilogue
    conv_hmma<1,2><<<dim3(160, 3, BATCH), 256, CONV_SMEM>>>(p3h, p3l, feat0, xb, 372, 384, 138, 80, 256, 3456, 1, u3b, wm2, 1);
    conv_small_part<3,0><<<dim3(160,4,BATCH),128>>>(xb, w3w, h3, 138, 4, 80, 256);
    finalize_small<<<(BATCH*3*20480+255)/256,256>>>(h3, w3b, mask2, 3, 80, 256, 1.f, BATCH*3*20480);
    idwt_k<<<dim3(80,1,BATCH),256>>>(ll80, h3, (float*)d_out, 80, 256);
}

// round 9
// speedup vs baseline: 2.8416x; 1.0355x over previous
#include <cuda_runtime.h>
#include <cuda_bf16.h>
#include <math.h>
#include <stdint.h>

#define BATCH 4

__device__ __forceinline__ uint32_t smem_u32(const void* p){
    uint32_t a; asm("{ .reg .u64 t; cvta.to.shared.u64 t, %1; cvt.u32.u64 %0, t; }":"=r"(a):"l"(p)); return a;
}
__device__ __forceinline__ void ldsm4(uint32_t& r0, uint32_t& r1, uint32_t& r2, uint32_t& r3, uint32_t a){
    asm volatile("ldmatrix.sync.aligned.m8n8.x4.shared.b16 {%0,%1,%2,%3}, [%4];"
        :"=r"(r0),"=r"(r1),"=r"(r2),"=r"(r3):"r"(a));
}
__device__ __forceinline__ void mma16816(float* c, const uint32_t* a, const uint32_t* b){
    asm volatile("mma.sync.aligned.m16n8k16.row.col.f32.bf16.bf16.f32 "
        "{%0,%1,%2,%3}, {%4,%5,%6,%7}, {%8,%9}, {%0,%1,%2,%3};"
        : "+f"(c[0]),"+f"(c[1]),"+f"(c[2]),"+f"(c[3])
        : "r"(a[0]),"r"(a[1]),"r"(a[2]),"r"(a[3]),"r"(b[0]),"r"(b[1]));
}
__device__ __forceinline__ void cpasync16(uint32_t saddr, const void* g){
    asm volatile("cp.async.cg.shared.global [%0], [%1], 16;"::"r"(saddr),"l"(g));
}
__device__ __forceinline__ void cpcommit(){ asm volatile("cp.async.commit_group;"); }
__device__ __forceinline__ void cpwait0(){ asm volatile("cp.async.wait_group 0;"); }
__device__ __forceinline__ uint32_t packf(float v){
    __nv_bfloat16 h = __float2bfloat16(v);
    __nv_bfloat16 l = __float2bfloat16(v - __bfloat162float(h));
    return (uint32_t)*(unsigned short*)&h | ((uint32_t)*(unsigned short*)&l << 16);
}

// ---------------- scratch ----------------
__device__ float g_xd0[BATCH*1104*10*32];
__device__ float g_xd1[BATCH*552*20*64];
__device__ float g_ll1[BATCH*20*64];
__device__ float g_h1[BATCH*3*20*64];
__device__ float g_ll40[BATCH*40*128];
__device__ float g_mask1[BATCH*20*64];
__device__ float g_upm1[BATCH*20*64];
__device__ float g_cam1[BATCH*40*128];
__device__ float g_wm1[BATCH*40*128];
__device__ float g_xa[BATCH*276*40*128];
__device__ float g_h2[BATCH*3*40*128];
__device__ float g_ll80[BATCH*80*256];
__device__ float g_mask2[BATCH*40*128];
__device__ float g_upm2[BATCH*40*128];
__device__ float g_cam2[BATCH*80*256];
__device__ float g_wm2[BATCH*80*256];
__device__ float g_xb[BATCH*138*80*256];
__device__ float g_h3[BATCH*3*80*256];
__device__ float g_thr[1];
// packed u32 (bf16 hi | lo<<16) conv inputs
__device__ __align__(16) uint32_t g_px32[BATCH*2208*10*32];
__device__ __align__(16) uint32_t g_cat1[BATCH*1488*20*64];
__device__ __align__(16) uint32_t g_feat1[BATCH*744*40*128];
__device__ __align__(16) uint32_t g_feat0[BATCH*372*80*256];
// packed weights (hi/lo planes), K reordered as t*ICpad+ic
__device__ __align__(16) __nv_bfloat16 g_w2h[1152*19872];
__device__ __align__(16) __nv_bfloat16 g_w2l[1152*19872];
__device__ __align__(16) __nv_bfloat16 g_u1h[640*13536];
__device__ __align__(16) __nv_bfloat16 g_u1l[640*13536];
__device__ __align__(16) __nv_bfloat16 g_u2h[384*6912];
__device__ __align__(16) __nv_bfloat16 g_u2l[384*6912];
__device__ __align__(16) __nv_bfloat16 g_u3h[256*3456];
__device__ __align__(16) __nv_bfloat16 g_u3l[256*3456];

// ---------------- weight pack: w[oc, ic*9+t] -> planes[ocpad, t*ICpad+ic] ----------------
__global__ void pack_w_k(const float* __restrict__ w, __nv_bfloat16* __restrict__ hi,
                         __nv_bfloat16* __restrict__ lo, int OC, int IC, int ICpad, int Kpad, int totRC)
{
    int i = blockIdx.x*256 + threadIdx.x;
    if (i >= totRC) return;
    int t = blockIdx.y;
    int r = i / ICpad, ic = i - r*ICpad;
    float v = (r < OC && ic < IC) ? w[(size_t)r*IC*9 + ic*9 + t] : 0.f;
    __nv_bfloat16 h = __float2bfloat16(v);
    size_t o = (size_t)r*Kpad + t*ICpad + ic;
    hi[o] = h;
    lo[o] = __float2bfloat16(v - __bfloat162float(h));
}

// ---------------- input pack ----------------
__global__ void pack_x_k(const float* __restrict__ x, uint32_t* __restrict__ o, int total)
{
    int i = blockIdx.x*256 + threadIdx.x;
    if (i < total) o[i] = packf(x[i]);
}

// ---------------- feat build + pack ----------------
__global__ void feat_pack_k(const float* __restrict__ xc, const float* __restrict__ skip,
                            const float* __restrict__ upm, const float* __restrict__ cam,
                            uint32_t* __restrict__ out, int C1, int C2, int Hf, int Wf, int total)
{
    int idx = blockIdx.x*256 + threadIdx.x;
    if (idx >= total) return;
    int Wc = Wf >> 1, Hc = Hf >> 1;
    int x = idx % Wf; int t = idx / Wf;
    int y = t % Hf;  t /= Hf;
    int c = t % (C1+C2); int b = t / (C1+C2);
    float v;
    if (c < C1) {
        v = xc[((size_t)b*C1 + c)*Hc*Wc + (size_t)(y>>1)*Wc + (x>>1)];
        if (upm) v *= upm[(size_t)b*Hc*Wc + (size_t)(y>>1)*Wc + (x>>1)];
    } else {
        v = skip[((size_t)b*C2 + (c-C1))*Hf*Wf + (size_t)y*Wf + x];
    }
    if (cam) v *= cam[(size_t)b*Hf*Wf + (size_t)y*Wf + x];
    out[idx] = packf(v);
}

// ---------------- HMMA implicit-GEMM conv: K-chunk 32, double-buffered, 2 CTA/SM ----------------
// ROWB must be a multiple of 16 (uint4/cp.async alignment). 80 = 64B data + 16B pad.
#define ROWB 80
#define S_AH 0
#define S_AL 10240
#define S_BH 20480
#define S_BL 30720
#define BUFSZ 40960
#define CONV_SMEM (2*BUFSZ)

template<int PAD, int MT>  // PAD: 1 reflect, 2 edge. M-tile = 32*MT rows.
__global__ __launch_bounds__(256, 2)
void conv_hmma(const __nv_bfloat16* __restrict__ Ah, const __nv_bfloat16* __restrict__ Al,
               const uint32_t* __restrict__ pin, float* __restrict__ out,
               int IC, int ICpad, int OC, int H, int W, int Kpad, int S,
               const float* __restrict__ bias, const float* __restrict__ mask, int leaky)
{
    extern __shared__ __align__(16) unsigned char sm[];
    const uint32_t sb = smem_u32(sm);
    const int tid = threadIdx.x, wid = tid >> 5, lane = tid & 31;
    const int HW = H * W;
    const int n0 = blockIdx.x * 128;
    const int Mtiles = gridDim.y / S;
    const int mt_id = blockIdx.y % Mtiles, ks = blockIdx.y / Mtiles;
    const int m0 = mt_id * (32*MT);
    const int b = blockIdx.z;

    const int chunks = Kpad >> 5;
    const int cseg = (chunks + S - 1) / S;
    const int c0 = ks * cseg, c1 = min(chunks, c0 + cseg);

    const uint32_t* inb = pin + (size_t)b * IC * HW;
    const int wm = (wid >> 2) * (16*MT), wn = (wid & 3) * 32;

    float acc[MT][4][4];
    #pragma unroll
    for (int i=0;i<MT;i++) for (int j=0;j<4;j++) for (int k=0;k<4;k++) acc[i][j][k]=0.f;

    const int mloc = tid >> 1, kh = tid & 1;
    const int nglob = n0 + mloc;
    const bool okpix = (nglob < HW);
    const int py = okpix ? nglob / W : 0;
    const int px_ = okpix ? nglob - py*W : 0;

    // tracker for NEXT chunk to gather (K reordered: k = t*ICpad + ic); per-thread k = c*32 + kh*16
    int kthr = (c0 << 5) + kh*16;
    int tap = kthr / ICpad;
    int icr = kthr - tap*ICpad;

    // ---- helpers ----
    auto issueA = [&](int c, int bo){
        const int kc = c << 5;
        #pragma unroll
        for (int i = 0; i < MT; ++i) {
            int flat = i*256 + tid;
            int fo = flat * 16;                 // byte index into 2*MT*2048 region
            int plane = fo / (MT*2048);
            int rem = fo - plane*(MT*2048);
            int row = rem >> 6, col = rem & 63; // 64B per row
            const __nv_bfloat16* src = (plane ? Al : Ah) + (size_t)(m0+row)*Kpad + kc + (col>>1);
            cpasync16(sb + bo + (plane ? S_AL : S_AH) + row*ROWB + col, src);
        }
        cpcommit();
    };
    auto gatherB = [&](int bo){
        int t3 = (tap*11) >> 5;
        int dy = t3 - 1, dx = tap - t3*3 - 1;
        int yy = py + dy, xx = px_ + dx;
        if (PAD == 1) {
            yy = yy<0 ? -yy : (yy>=H ? 2*H-2-yy : yy);
            xx = xx<0 ? -xx : (xx>=W ? 2*W-2-xx : xx);
        } else {
            yy = min(max(yy,0),H-1); xx = min(max(xx,0),W-1);
        }
        const uint32_t* p = inb + (size_t)icr*HW + yy*W + xx;
        int d = bo + mloc*ROWB + kh*32;
        #pragma unroll
        for (int g8 = 0; g8 < 2; ++g8) {
            uint32_t v[8];
            #pragma unroll
            for (int e = 0; e < 8; ++e)
                v[e] = (okpix && (icr + g8*8 + e) < IC) ? __ldg(p + (size_t)(g8*8+e)*HW) : 0u;
            uint32_t hp0 = __byte_perm(v[0],v[1],0x5410), hp1 = __byte_perm(v[2],v[3],0x5410);
            uint32_t hp2 = __byte_perm(v[4],v[5],0x5410), hp3 = __byte_perm(v[6],v[7],0x5410);
            uint32_t lp0 = __byte_perm(v[0],v[1],0x7632), lp1 = __byte_perm(v[2],v[3],0x7632);
            uint32_t lp2 = __byte_perm(v[4],v[5],0x7632), lp3 = __byte_perm(v[6],v[7],0x7632);
            *(uint4*)(sm + d + S_BH + g8*16) = make_uint4(hp0,hp1,hp2,hp3);
            *(uint4*)(sm + d + S_BL + g8*16) = make_uint4(lp0,lp1,lp2,lp3);
        }
        icr += 32;
        if (icr >= ICpad) { icr -= ICpad; ++tap; }
    };

    // ---- prologue: fill buffer 0 with chunk c0 ----
    issueA(c0, 0);
    gatherB(0);

    for (int c = c0; c < c1; ++c) {
        const int bo = ((c - c0) & 1) * BUFSZ;
        const int bn = BUFSZ - bo;
        cpwait0();
        __syncthreads();          // chunk c resident in bo; bn free for writes
        if (c + 1 < c1) {
            issueA(c + 1, bn);
            gatherB(bn);
        }
        // ---- compute on buffer bo: 2 k16 steps ----
        #pragma unroll
        for (int kk = 0; kk < 2; ++kk) {
            uint32_t bh[4][2], bl[4][2];
            #pragma unroll
            for (int nt2 = 0; nt2 < 2; ++nt2) {
                int g = lane >> 3;
                int brow = wn + nt2*16 + (lane & 7) + ((g & 2) ? 8 : 0);
                uint32_t baddr = sb + bo + brow*ROWB + kk*32 + ((g & 1) ? 16 : 0);
                ldsm4(bh[nt2*2][0], bh[nt2*2][1], bh[nt2*2+1][0], bh[nt2*2+1][1], baddr + S_BH);
                ldsm4(bl[nt2*2][0], bl[nt2*2][1], bl[nt2*2+1][0], bl[nt2*2+1][1], baddr + S_BL);
            }
            #pragma unroll
            for (int mt = 0; mt < MT; ++mt) {
                int arow = wm + mt*16 + (lane & 15);
                uint32_t aaddr = sb + bo + arow*ROWB + kk*32 + ((lane >> 4) ? 16 : 0);
                uint32_t ah[4], al[4];
                ldsm4(ah[0], ah[1], ah[2], ah[3], aaddr + S_AH);
                ldsm4(al[0], al[1], al[2], al[3], aaddr + S_AL);
                #pragma unroll
                for (int nt = 0; nt < 4; ++nt) {
                    mma16816(acc[mt][nt], ah, bh[nt]);
                    mma16816(acc[mt][nt], ah, bl[nt]);
                    mma16816(acc[mt][nt], al, bh[nt]);
                }
            }
        }
    }

    // ---- epilogue ----
    float* ob = out + (size_t)b * OC * HW;
    const float* mb = mask ? mask + (size_t)b*HW : nullptr;
    const bool direct = (S == 1);
    #pragma unroll
    for (int mt = 0; mt < MT; ++mt) {
        #pragma unroll
        for (int nt = 0; nt < 4; ++nt) {
            #pragma unroll
            for (int cr = 0; cr < 4; ++cr) {
                int r = wm + mt*16 + (lane >> 2) + ((cr >= 2) ? 8 : 0);
                int col = wn + nt*8 + (lane & 3)*2 + (cr & 1);
                int oc = m0 + r, px = n0 + col;
                if (oc < OC && px < HW) {
                    float v = acc[mt][nt][cr];
                    if (direct) {
                        if (bias) v += bias[oc];
                        if (leaky) v = v > 0.f ? v : 0.2f*v;
                        if (mb) v *= mb[px];
                        ob[(size_t)oc*HW + px] = v;
                    } else {
                        atomicAdd(ob + (size_t)oc*HW + px, v);
                    }
                }
            }
        }
    }
}

// ---------------- finalize big ----------------
__global__ void finalize_big(float* __restrict__ buf, const float* __restrict__ bias,
                             const float* __restrict__ mask, int C, int HW, int leaky, int total)
{
    int i = blockIdx.x*256 + threadIdx.x;
    if (i >= total) return;
    int p = i % HW, t = i / HW, c = t % C, b = t / C;
    float v = buf[i] + bias[c];
    if (leaky) v = v > 0.f ? v : 0.2f*v;
    if (mask) v *= mask[(size_t)b*HW + p];
    buf[i] = v;
}

// ---------------- small conv partial ----------------
template<int NOUT, int PAD>
__global__ void conv_small_part(const float* __restrict__ in, const float* __restrict__ wgt,
                                float* __restrict__ acc, int IC, int nsp, int H, int W)
{
    int b = blockIdx.z, sp = blockIdx.y;
    int HW = H*W;
    int p = blockIdx.x*128 + threadIdx.x;
    if (p >= HW) return;
    int y = p / W, x = p - y*W;
    int icPer = (IC + nsp - 1)/nsp, ic0 = sp*icPer, ic1 = min(IC, ic0+icPer);
    float a[NOUT];
    #pragma unroll
    for (int j = 0; j < NOUT; ++j) a[j] = 0.f;
    const float* inb = in + (size_t)b*IC*HW;
    for (int ic = ic0; ic < ic1; ++ic) {
        const float* ip = inb + (size_t)ic*HW;
        const float* wp = wgt + (size_t)ic*9;
        #pragma unroll
        for (int t = 0; t < 9; ++t) {
            int yy = y + t/3 - 1, xx = x + t%3 - 1;
            float v;
            if (PAD == 0) v = (yy>=0 && yy<H && xx>=0 && xx<W) ? __ldg(ip + yy*W + xx) : 0.f;
            else { yy = min(max(yy,0),H-1); xx = min(max(xx,0),W-1); v = __ldg(ip + yy*W + xx); }
            #pragma unroll
            for (int j = 0; j < NOUT; ++j)
                a[j] = fmaf(v, __ldg(wp + (size_t)j*IC*9 + t), a[j]);
        }
    }
    #pragma unroll
    for (int j = 0; j < NOUT; ++j)
        atomicAdd(acc + ((size_t)b*NOUT + j)*HW + p, a[j]);
}

__global__ void finalize_small(float* __restrict__ buf, const float* __restrict__ bias,
                               const float* __restrict__ mask, int NOUT, int H, int W,
                               float scale, int total)
{
    int i = blockIdx.x*256 + threadIdx.x;
    if (i >= total) return;
    int HW = H*W;
    int p = i % HW, t = i / HW, c = t % NOUT, b = t / NOUT;
    float v = (buf[i] + bias[c]) * scale;
    if (mask) {
        int y = p / W, x = p - y*W;
        v *= mask[(size_t)b*(HW/4) + (y>>1)*(W>>1) + (x>>1)];
    }
    buf[i] = v;
}

// ---------------- glue ----------------
__global__ void idwt_k(const float* __restrict__ ll, const float* __restrict__ h,
                       float* __restrict__ out, int Hc, int Wc)
{
    int b = blockIdx.z;
    int p = blockIdx.x*256 + threadIdx.x;
    if (p >= Hc*Wc) return;
    int y = p / Wc, x = p - y*Wc;
    float l = ll[(size_t)b*Hc*Wc + p];
    const float* hb = h + (size_t)b*3*Hc*Wc;
    float lh = hb[p], hl = hb[Hc*Wc+p], hh = hb[2*Hc*Wc+p];
    float a = (l+lh)*0.5f, c2 = (l-lh)*0.5f, d2 = (hl+hh)*0.5f, e = (hl-hh)*0.5f;
    float* ob = out + (size_t)b*(2*Hc)*(2*Wc);
    int W2 = 2*Wc;
    ob[(size_t)(2*y)*W2 + 2*x]     = a + d2;
    ob[(size_t)(2*y)*W2 + 2*x+1]   = c2 + e;
    ob[(size_t)(2*y+1)*W2 + 2*x]   = a - d2;
    ob[(size_t)(2*y+1)*W2 + 2*x+1] = c2 - e;
}
__global__ void minmax_k(const float* __restrict__ d, int n, float* __restrict__ thr)
{
    __shared__ float smn[1024], smx[1024];
    int tid = threadIdx.x;
    float mn = 3.4e38f, mx = -3.4e38f;
    for (int i = tid; i < n; i += 1024) { float v = d[i]; mn = fminf(mn,v); mx = fmaxf(mx,v); }
    smn[tid]=mn; smx[tid]=mx; __syncthreads();
    for (int s=512; s>0; s>>=1) {
        if (tid<s){ smn[tid]=fminf(smn[tid],smn[tid+s]); smx[tid]=fmaxf(smx[tid],smx[tid+s]); }
        __syncthreads();
    }
    if (tid==0) thr[0] = (smx[0]-smn[0])*0.1f;
}
__global__ void mask_k(const float* __restrict__ h, const float* __restrict__ thr,
                       float* __restrict__ mask, int Hc, int Wc)
{
    int b = blockIdx.z;
    int p = blockIdx.x*256 + threadIdx.x;
    if (p >= Hc*Wc) return;
    const float* hb = h + (size_t)b*3*Hc*Wc;
    float m = fmaxf(fabsf(hb[p]), fmaxf(fabsf(hb[Hc*Wc+p]), fabsf(hb[2*Hc*Wc+p])));
    mask[(size_t)b*Hc*Wc + p] = (m > thr[0]) ? 1.f : 0.f;
}
__global__ void pool_coarse_k(const float* __restrict__ mask, float* __restrict__ upm, int Hc, int Wc)
{
    int b = blockIdx.z;
    int p = blockIdx.x*256 + threadIdx.x;
    if (p >= Hc*Wc) return;
    int y = p / Wc, x = p - y*Wc;
    const float* mb = mask + (size_t)b*Hc*Wc;
    float r = 0.f;
    for (int dy=-2;dy<=2;dy++){ int yy=y+dy; if (yy<0||yy>=Hc) continue;
      for (int dx=-2;dx<=2;dx++){ int xx=x+dx; if (xx<0||xx>=Wc) continue;
        r = fmaxf(r, mb[yy*Wc+xx]); } }
    upm[(size_t)b*Hc*Wc + p] = (r > 0.f) ? 1.f : 0.f;
}
__global__ void pool_fine_k(const float* __restrict__ mask, float* __restrict__ cam,
                            float* __restrict__ wm, int Hc, int Wc)
{
    int b = blockIdx.z;
    int Hf = 2*Hc, Wf = 2*Wc;
    int p = blockIdx.x*256 + threadIdx.x;
    if (p >= Hf*Wf) return;
    int y = p / Wf, x = p - y*Wf;
    const float* mb = mask + (size_t)b*Hc*Wc;
    float c5 = 0.f, c3 = 0.f;
    for (int dy=-2;dy<=2;dy++){ int fy=y+dy; if (fy<0||fy>=Hf) continue;
      for (int dx=-2;dx<=2;dx++){ int fx=x+dx; if (fx<0||fx>=Wf) continue;
        float v = mb[(fy>>1)*Wc + (fx>>1)];
        c5 = fmaxf(c5, v);
        if (dy>=-1 && dy<=1 && dx>=-1 && dx<=1) c3 = fmaxf(c3, v);
      } }
    cam[(size_t)b*Hf*Wf + p] = (c5 > 0.f) ? 1.f : 0.f;
    wm [(size_t)b*Hf*Wf + p] = (c3 > 0.f) ? 1.f : 0.f;
}

// =======================================================================
extern "C" void kernel_launch(void* const* d_in, const int* in_sizes, int n_in,
                              void* d_out, int out_size)
{
    const float* x32 = (const float*)d_in[0];
    const float* x16 = (const float*)d_in[1];
    const float* x8  = (const float*)d_in[2];
    const float* x4  = (const float*)d_in[3];
    const float* c2w = (const float*)d_in[4];  const float* c2b = (const float*)d_in[5];
    const float* u1w = (const float*)d_in[6];  const float* u1b = (const float*)d_in[7];
    const float* wllw= (const float*)d_in[8];  const float* wllb= (const float*)d_in[9];
    const float* w1w = (const float*)d_in[10]; const float* w1b = (const float*)d_in[11];
    const float* u2w = (const float*)d_in[12]; const float* u2b = (const float*)d_in[13];
    const float* w2w = (const float*)d_in[14]; const float* w2b = (const float*)d_in[15];
    const float* u3w = (const float*)d_in[16]; const float* u3b = (const float*)d_in[17];
    const float* w3w = (const float*)d_in[18]; const float* w3b = (const float*)d_in[19];

    float *xd0,*xd1,*ll1,*h1,*ll40,*mask1,*upm1,*cam1,*wm1;
    float *xa,*h2,*ll80,*mask2,*upm2,*cam2,*wm2,*xb,*h3,*thr;
    uint32_t *px32,*cat1,*feat1,*feat0;
    __nv_bfloat16 *w2h,*w2l,*p1h,*p1l,*p2h,*p2l,*p3h,*p3l;
    cudaGetSymbolAddress((void**)&xd0,g_xd0);   cudaGetSymbolAddress((void**)&xd1,g_xd1);
    cudaGetSymbolAddress((void**)&ll1,g_ll1);   cudaGetSymbolAddress((void**)&h1,g_h1);
    cudaGetSymbolAddress((void**)&ll40,g_ll40); cudaGetSymbolAddress((void**)&mask1,g_mask1);
    cudaGetSymbolAddress((void**)&upm1,g_upm1); cudaGetSymbolAddress((void**)&cam1,g_cam1);
    cudaGetSymbolAddress((void**)&wm1,g_wm1);   cudaGetSymbolAddress((void**)&xa,g_xa);
    cudaGetSymbolAddress((void**)&h2,g_h2);     cudaGetSymbolAddress((void**)&ll80,g_ll80);
    cudaGetSymbolAddress((void**)&mask2,g_mask2); cudaGetSymbolAddress((void**)&upm2,g_upm2);
    cudaGetSymbolAddress((void**)&cam2,g_cam2); cudaGetSymbolAddress((void**)&wm2,g_wm2);
    cudaGetSymbolAddress((void**)&xb,g_xb);     cudaGetSymbolAddress((void**)&h3,g_h3);
    cudaGetSymbolAddress((void**)&thr,g_thr);
    cudaGetSymbolAddress((void**)&px32,g_px32); cudaGetSymbolAddress((void**)&cat1,g_cat1);
    cudaGetSymbolAddress((void**)&feat1,g_feat1); cudaGetSymbolAddress((void**)&feat0,g_feat0);
    cudaGetSymbolAddress((void**)&w2h,g_w2h);   cudaGetSymbolAddress((void**)&w2l,g_w2l);
    cudaGetSymbolAddress((void**)&p1h,g_u1h);   cudaGetSymbolAddress((void**)&p1l,g_u1l);
    cudaGetSymbolAddress((void**)&p2h,g_u2h);   cudaGetSymbolAddress((void**)&p2l,g_u2l);
    cudaGetSymbolAddress((void**)&p3h,g_u3h);   cudaGetSymbolAddress((void**)&p3l,g_u3l);

    cudaFuncSetAttribute(conv_hmma<1,4>, cudaFuncAttributeMaxDynamicSharedMemorySize, CONV_SMEM);
    cudaFuncSetAttribute(conv_hmma<2,4>, cudaFuncAttributeMaxDynamicSharedMemorySize, CONV_SMEM);
    cudaFuncSetAttribute(conv_hmma<1,2>, cudaFuncAttributeMaxDynamicSharedMemorySize, CONV_SMEM);

    // pack weights. ICpad: 2208,1504,768,384 ; Kpad: 19872,13536,6912,3456
    { int t=1152*2208; pack_w_k<<<dim3((t+255)/256,9),256>>>(c2w, w2h, w2l, 1104, 2208, 2208, 19872, t); }
    { int t=640*1504;  pack_w_k<<<dim3((t+255)/256,9),256>>>(u1w, p1h, p1l, 552, 1488, 1504, 13536, t); }
    { int t=384*768;   pack_w_k<<<dim3((t+255)/256,9),256>>>(u2w, p2h, p2l, 276, 744, 768, 6912, t); }
    { int t=256*384;   pack_w_k<<<dim3((t+255)/256,9),256>>>(u3w, p3h, p3l, 138, 372, 384, 3456, t); }

    { int t=BATCH*2208*320; pack_x_k<<<(t+255)/256,256>>>(x32, px32, t); }

    cudaMemsetAsync(xd0, 0, sizeof(g_xd0), 0);
    cudaMemsetAsync(xd1, 0, sizeof(g_xd1), 0);
    cudaMemsetAsync(ll1, 0, sizeof(g_ll1), 0);
    cudaMemsetAsync(h1,  0, sizeof(g_h1), 0);
    cudaMemsetAsync(h2,  0, sizeof(g_h2), 0);
    cudaMemsetAsync(h3,  0, sizeof(g_h3), 0);

    // conv2 (edge): 2208->1104, 10x32, Mtiles=9, S=4
    conv_hmma<2,4><<<dim3(3, 9*4, BATCH), 256, CONV_SMEM>>>(w2h, w2l, px32, xd0, 2208, 2208, 1104, 10, 32, 19872, 4, nullptr, nullptr, 0);
    finalize_big<<<(BATCH*1104*320+255)/256,256>>>(xd0, c2b, nullptr, 1104, 320, 0, BATCH*1104*320);
    { int t = BATCH*1488*20*64;
      feat_pack_k<<<(t+255)/256,256>>>(xd0, x16, nullptr, nullptr, cat1, 1104, 384, 20, 64, t); }
    // up1 (reflect): 1488->552, Mtiles=5, S=2
    conv_hmma<1,4><<<dim3(10, 5*2, BATCH), 256, CONV_SMEM>>>(p1h, p1l, cat1, xd1, 1488, 1504, 552, 20, 64, 13536, 2, nullptr, nullptr, 0);
    finalize_big<<<(BATCH*552*1280+255)/256,256>>>(xd1, u1b, nullptr, 552, 1280, 1, BATCH*552*1280);
    conv_small_part<1,2><<<dim3(10,12,BATCH),128>>>(xd1, wllw, ll1, 552, 12, 20, 64);
    conv_small_part<3,0><<<dim3(10,12,BATCH),128>>>(xd1, w1w, h1, 552, 12, 20, 64);
    finalize_small<<<(BATCH*1280+255)/256,256>>>(ll1, wllb, nullptr, 1, 20, 64, 8.f, BATCH*1280);
    finalize_small<<<(BATCH*3*1280+255)/256,256>>>(h1, w1b, nullptr, 3, 20, 64, 4.f, BATCH*3*1280);
    idwt_k<<<dim3(5,1,BATCH),256>>>(ll1, h1, ll40, 20, 64);
    minmax_k<<<1,1024>>>(ll40, BATCH*40*128, thr);
    mask_k<<<dim3(5,1,BATCH),256>>>(h1, thr, mask1, 20, 64);
    pool_coarse_k<<<dim3(5,1,BATCH),256>>>(mask1, upm1, 20, 64);
    pool_fine_k<<<dim3(20,1,BATCH),256>>>(mask1, cam1, wm1, 20, 64);
    { int t = BATCH*744*40*128;
      feat_pack_k<<<(t+255)/256,256>>>(xd1, x8, upm1, cam1, feat1, 552, 192, 40, 128, t); }
    // up2 (reflect): 744->276, Mtiles=3, S=1, fused epilogue
    conv_hmma<1,4><<<dim3(40, 3, BATCH), 256, CONV_SMEM>>>(p2h, p2l, feat1, xa, 744, 768, 276, 40, 128, 6912, 1, u2b, wm1, 1);
    conv_small_part<3,0><<<dim3(40,8,BATCH),128>>>(xa, w2w, h2, 276, 8, 40, 128);
    finalize_small<<<(BATCH*3*5120+255)/256,256>>>(h2, w2b, mask1, 3, 40, 128, 2.f, BATCH*3*5120);
    idwt_k<<<dim3(20,1,BATCH),256>>>(ll40, h2, ll80, 40, 128);
    minmax_k<<<1,1024>>>(ll80, BATCH*80*256, thr);
    mask_k<<<dim3(20,1,BATCH),256>>>(h2, thr, mask2, 40, 128);
    pool_coarse_k<<<dim3(20,1,BATCH),256>>>(mask2, upm2, 40, 128);
    pool_fine_k<<<dim3(80,1,BATCH),256>>>(mask2, cam2, wm2, 40, 128);
    { int t = BATCH*372*80*256;
      feat_pack_k<<<(t+255)/256,256>>>(xa, x4, upm2, cam2, feat0, 276, 96, 80, 256, t); }
    // up3 (reflect): 372->138, M-tile=64, Mtiles=3, S=1, fused epilogue
    conv_hmma<1,2><<<dim3(160, 3, BATCH), 256, CONV_SMEM>>>(p3h, p3l, feat0, xb, 372, 384, 138, 80, 256, 3456, 1, u3b, wm2, 1);
    conv_small_part<3,0><<<dim3(160,4,BATCH),128>>>(xb, w3w, h3, 138, 4, 80, 256);
    finalize_small<<<(BATCH*3*20480+255)/256,256>>>(h3, w3b, mask2, 3, 80, 256, 1.f, BATCH*3*20480);
    idwt_k<<<dim3(80,1,BATCH),256>>>(ll80, h3, (float*)d_out, 80, 256);
}